// round 11
// baseline (speedup 1.0000x reference)
#include <cuda_runtime.h>
#include <cuda_bf16.h>
#include <math.h>
#include <stdint.h>

#define NB     4096          // batch rows
#define K_EXT  7936          // 7808 + 128 (h0 folded in)
#define N_G    512           // 4*LSTM_HIDDEN
#define TM     128
#define TN     64
#define BK     32
#define NSTAGE 3
#define NT     (K_EXT/BK)    // 248

// ---- scratch (device globals: allocation-free rule) ----
__device__ __align__(16) __nv_bfloat16 g_eah[300 * 128];   // ability emb hi
__device__ __align__(16) __nv_bfloat16 g_eal[300 * 128];   // ability emb lo
__device__ __align__(16) __nv_bfloat16 g_emh[900 * 128];   // move emb hi
__device__ __align__(16) __nv_bfloat16 g_eml[900 * 128];   // move emb lo
__device__ __align__(16) __nv_bfloat16 g_exh[(size_t)NB * 256];  // [num | h0] hi
__device__ __align__(16) __nv_bfloat16 g_exl[(size_t)NB * 256];  // [num | h0] lo
__device__ __align__(16) __nv_bfloat16 g_wh[(size_t)N_G * K_EXT];  // W hi [N][K]
__device__ __align__(16) __nv_bfloat16 g_wl[(size_t)N_G * K_EXT];  // W lo
__device__ __align__(16) float         g_gates[(size_t)NB * N_G];  // fp32 gates (no bias)

__device__ __forceinline__ void split2(float v, __nv_bfloat16& h, __nv_bfloat16& l) {
    h = __float2bfloat16(v);
    l = __float2bfloat16(v - __bfloat162float(h));
}

// ============================================================
// 1) pack: embpack + extrapack + wpack merged (block-range dispatch)
//    blocks [0,128): extrapack (numproj + h0, 32 batch rows each)
//    blocks [128,728): embpack (2 table rows each)
//    blocks [728,1240): wpack (1 weight row each)
// ============================================================
#define EX_SMEM ((128 * 85 + 32 * 84) * 4)   // 54272 bytes

__global__ __launch_bounds__(256)
void pack_kernel(const float* __restrict__ aemb, const float* __restrict__ memb,
                 const float* __restrict__ numerical, const float* __restrict__ num_W,
                 const float* __restrict__ num_b, const float* __restrict__ h0,
                 const float* __restrict__ Wih, const float* __restrict__ Whh)
{
    const int bx = blockIdx.x;
    const int tid = threadIdx.x;

    if (bx < 128) {
        // ---- extrapack: numproj + h0 -> [B][256] bf16 hi/lo ----
        extern __shared__ float exsm[];
        float* Ws  = exsm;               // [128][85]
        float* nrs = exsm + 128 * 85;    // [32][84]
        const int m0 = bx * 32;

        for (int i = tid; i < 128 * 84; i += 256) {
            int t = i / 84, d = i - t * 84;
            Ws[t * 85 + d] = num_W[i];
        }
        for (int i = tid; i < 32 * 84; i += 256)
            nrs[i] = numerical[(size_t)m0 * 84 + i];
        __syncthreads();

        const int t = tid & 127, rbase = tid >> 7;
        const float nb = num_b[t];
        const float* w = Ws + t * 85;
        for (int rr = rbase; rr < 32; rr += 2) {
            const float* nr = nrs + rr * 84;
            float acc = nb;
            #pragma unroll 4
            for (int d = 0; d < 84; d++) acc += w[d] * nr[d];
            __nv_bfloat16 h, l;
            split2(acc, h, l);
            g_exh[(size_t)(m0 + rr) * 256 + t] = h;
            g_exl[(size_t)(m0 + rr) * 256 + t] = l;
        }
        for (int i = tid; i < 32 * 128; i += 256) {
            int r = i >> 7, d = i & 127;
            __nv_bfloat16 h, l;
            split2(h0[(size_t)(m0 + r) * 128 + d], h, l);
            g_exh[(size_t)(m0 + r) * 256 + 128 + d] = h;
            g_exl[(size_t)(m0 + r) * 256 + 128 + d] = l;
        }
    } else if (bx < 728) {
        // ---- embpack: 2 rows of the emb tables per block ----
        const int r2 = (bx - 128) * 2;
        const int r = r2 + (tid >> 7), t = tid & 127;
        __nv_bfloat16 h, l;
        if (r < 300) {
            split2(aemb[r * 128 + t], h, l);
            g_eah[r * 128 + t] = h;
            g_eal[r * 128 + t] = l;
        } else {
            int rr = r - 300;
            split2(memb[rr * 128 + t], h, l);
            g_emh[rr * 128 + t] = h;
            g_eml[rr * 128 + t] = l;
        }
    } else {
        // ---- wpack: one [Wih|Whh] row -> bf16 hi/lo ----
        const int n = bx - 728;
        for (int i4 = tid; i4 < K_EXT / 4; i4 += 256) {
            int k = i4 * 4;
            float4 v = (k < 7808) ? *(const float4*)(Wih + (size_t)n * 7808 + k)
                                  : *(const float4*)(Whh + n * 128 + (k - 7808));
            __nv_bfloat16 h0_, h1_, h2_, h3_, l0_, l1_, l2_, l3_;
            split2(v.x, h0_, l0_); split2(v.y, h1_, l1_);
            split2(v.z, h2_, l2_); split2(v.w, h3_, l3_);
            __nv_bfloat162 ph01{h0_, h1_}, ph23{h2_, h3_}, pl01{l0_, l1_}, pl23{l2_, l3_};
            uint2 uh, ul;
            uh.x = *(uint32_t*)&ph01; uh.y = *(uint32_t*)&ph23;
            ul.x = *(uint32_t*)&pl01; ul.y = *(uint32_t*)&pl23;
            size_t off = (size_t)n * K_EXT + k;
            *(uint2*)(g_wh + off) = uh;
            *(uint2*)(g_wl + off) = ul;
        }
    }
}

// ============================================================
// 2) GEMM: gates[4096][512] = x @ W^T (3-term bf16 split)
//    CTA 128x64, 128 threads, warp tile 64x32 (2x2 warp grid), BK=32,
//    cp.async 3-stage. All 24 LDSMs for both 16-K subs issued up front,
//    then 96 back-to-back MMAs (single latency exposure per stage).
//    A gathered on-the-fly from emb tables via smem id table.
// ============================================================
#define LDP 40                          // padded leading dim (elements)
#define A_STAGE_B (TM * LDP * 2)        // 10240 bytes per (hi|lo)
#define B_STAGE_B (TN * LDP * 2)        // 5120 bytes per (hi|lo)
#define OFF_AL    (A_STAGE_B)           // 10240
#define OFF_BH    (2 * A_STAGE_B)       // 20480
#define OFF_BL    (2 * A_STAGE_B + B_STAGE_B)  // 25600
#define STAGE_B   (2 * A_STAGE_B + 2 * B_STAGE_B)  // 30720
#define IDS_B     (128 * 60 * 2)        // 15360 (u16 id table)
#define SM_STG    IDS_B
#define GEMM_SMEM (IDS_B + NSTAGE * STAGE_B)   // 107520

__device__ __forceinline__ uint32_t smem_u32(const void* p) {
    uint32_t a;
    asm("{ .reg .u64 t; cvta.to.shared.u64 t, %1; cvt.u32.u64 %0, t; }" : "=r"(a) : "l"(p));
    return a;
}
__device__ __forceinline__ void cp16(uint32_t s, const void* g) {
    asm volatile("cp.async.cg.shared.global [%0], [%1], 16;" :: "r"(s), "l"(g));
}
#define LDSM4(r, addr) \
    asm volatile("ldmatrix.sync.aligned.m8n8.x4.shared.b16 {%0,%1,%2,%3}, [%4];" \
        : "=r"((r)[0]), "=r"((r)[1]), "=r"((r)[2]), "=r"((r)[3]) : "r"(addr))
#define MMA16816(c, a, b0, b1) \
    asm volatile("mma.sync.aligned.m16n8k16.row.col.f32.bf16.bf16.f32 " \
        "{%0,%1,%2,%3}, {%4,%5,%6,%7}, {%8,%9}, {%0,%1,%2,%3};" \
        : "+f"((c)[0]), "+f"((c)[1]), "+f"((c)[2]), "+f"((c)[3]) \
        : "r"((a)[0]), "r"((a)[1]), "r"((a)[2]), "r"((a)[3]), "r"(b0), "r"(b1))

__global__ __launch_bounds__(128, 2)
void gemm_kernel(const int* __restrict__ aid, const int* __restrict__ mid)
{
    extern __shared__ char smbase[];
    const uint32_t sb = smem_u32(smbase);
    const int tid = threadIdx.x;
    const int n0 = blockIdx.x * TN;
    const int m0 = blockIdx.y * TM;

    // ---- load id table: sid[r][0..11]=ability, sid[r][12..59]=move ----
    uint16_t* sid = (uint16_t*)smbase;
    {
        const int* asrc = aid + (size_t)m0 * 12;     // 1536 contiguous ints
        const int* msrc = mid + (size_t)m0 * 48;     // 6144 contiguous ints
        for (int i = tid; i < 1536; i += 128) {
            int r = i / 12, s = i % 12;
            sid[r * 60 + s] = (uint16_t)asrc[i];
        }
        for (int i = tid; i < 6144; i += 128) {
            int r = i / 48, s = i % 48;
            sid[r * 60 + 12 + s] = (uint16_t)msrc[i];
        }
    }
    __syncthreads();

    // ---- per-thread cp.async roles: A rows r0+{0,32,64,96}, B rows r0+{0,32}, chunk c ----
    const int r0 = tid >> 2;             // 0..31
    const int c  = tid & 3;              // 16B chunk within 64B k-row
    uint32_t soff_a[4], soff_b[2];
    #pragma unroll
    for (int q = 0; q < 4; q++) soff_a[q] = (r0 + 32 * q) * (LDP * 2) + c * 16;
    #pragma unroll
    for (int q = 0; q < 2; q++) soff_b[q] = OFF_BH + (r0 + 32 * q) * (LDP * 2) + c * 16;
    const char* bsrc_h[2] = {
        (const char*)(g_wh + (size_t)(n0 + r0) * K_EXT) + c * 16,
        (const char*)(g_wh + (size_t)(n0 + r0 + 32) * K_EXT) + c * 16 };
    const char* bsrc_l[2] = {
        (const char*)(g_wl + (size_t)(n0 + r0) * K_EXT) + c * 16,
        (const char*)(g_wl + (size_t)(n0 + r0 + 32) * K_EXT) + c * 16 };

    auto prefetch = [&](int ss, int buf) {
        const uint32_t dst = sb + SM_STG + buf * STAGE_B;
        const int k = ss * BK + c * 8;
        #pragma unroll
        for (int q = 0; q < 4; q++) {
            const int rr = r0 + 32 * q;
            const char *ah, *al;
            if (k < 7680) {
                const int s = k >> 7, d = k & 127;
                const int id = sid[rr * 60 + s];
                if (s < 12) {
                    ah = (const char*)(g_eah + id * 128 + d);
                    al = (const char*)(g_eal + id * 128 + d);
                } else {
                    ah = (const char*)(g_emh + id * 128 + d);
                    al = (const char*)(g_eml + id * 128 + d);
                }
            } else {
                const int d = k - 7680;
                ah = (const char*)(g_exh + (size_t)(m0 + rr) * 256 + d);
                al = (const char*)(g_exl + (size_t)(m0 + rr) * 256 + d);
            }
            cp16(dst + soff_a[q], ah);
            cp16(dst + OFF_AL + soff_a[q], al);
        }
        const size_t bk = (size_t)ss * (BK * 2);
        #pragma unroll
        for (int q = 0; q < 2; q++) {
            cp16(dst + soff_b[q], bsrc_h[q] + bk);
            cp16(dst + (OFF_BL - OFF_BH) + soff_b[q], bsrc_l[q] + bk);
        }
        asm volatile("cp.async.commit_group;" ::: "memory");
    };

    const int wid = tid >> 5;
    const int lane = tid & 31;
    const int wm = wid & 1;              // 2 warps along M (64 rows each)
    const int wn = wid >> 1;             // 2 warps along N (32 cols each)

    // ---- ldmatrix lane-address element offsets (within stage, in elements) ----
    const int arow = lane & 15;
    const int akh  = (lane >> 4) << 3;
    int aoff[4];
    #pragma unroll
    for (int i = 0; i < 4; i++)
        aoff[i] = (wm * 64 + i * 16 + arow) * LDP + akh;
    const int bn  = (lane & 7) + ((lane >> 4) << 3);
    const int bkh = ((lane >> 3) & 1) << 3;
    int boff[2];
    #pragma unroll
    for (int p = 0; p < 2; p++)
        boff[p] = (wn * 32 + p * 16 + bn) * LDP + bkh;

    float acc[4][4][4];   // [m-tile][n8-tile][frag]
    #pragma unroll
    for (int i = 0; i < 4; i++)
        #pragma unroll
        for (int j = 0; j < 4; j++)
            #pragma unroll
            for (int q = 0; q < 4; q++) acc[i][j][q] = 0.0f;

    // ---- prologue: stages 0,1 in flight ----
    prefetch(0, 0);
    prefetch(1, 1);

    #pragma unroll 1
    for (int t = 0; t < NT; ++t) {
        asm volatile("cp.async.wait_group 1;" ::: "memory");
        __syncthreads();   // stage t visible; all warps done with stage t-1

        if (t + 2 < NT) {
            prefetch(t + 2, (t + 2) % NSTAGE);
        } else {
            asm volatile("cp.async.commit_group;" ::: "memory");  // keep group count uniform
        }

        const uint32_t stg_u = sb + SM_STG + (t % NSTAGE) * STAGE_B;
        const uint32_t Ah_u = stg_u;
        const uint32_t Al_u = stg_u + OFF_AL;
        const uint32_t Bh_u = stg_u + OFF_BH;
        const uint32_t Bl_u = stg_u + OFF_BL;

        // ---- all 24 LDSM.x4 for BOTH 16-K subs up front (single latency exposure) ----
        uint32_t ah[2][4][4], al[2][4][4], bh[2][2][4], bl[2][2][4];
        #pragma unroll
        for (int sub = 0; sub < 2; sub++) {
            const int k16 = sub * 16;
            #pragma unroll
            for (int i = 0; i < 4; i++) {
                LDSM4(ah[sub][i], Ah_u + (uint32_t)(aoff[i] + k16) * 2);
                LDSM4(al[sub][i], Al_u + (uint32_t)(aoff[i] + k16) * 2);
            }
            #pragma unroll
            for (int p = 0; p < 2; p++) {
                LDSM4(bh[sub][p], Bh_u + (uint32_t)(boff[p] + k16) * 2);
                LDSM4(bl[sub][p], Bl_u + (uint32_t)(boff[p] + k16) * 2);
            }
        }
        // ---- 96 back-to-back MMAs across 16 independent accumulator tiles ----
        #pragma unroll
        for (int sub = 0; sub < 2; sub++)
            #pragma unroll
            for (int i = 0; i < 4; i++)
                #pragma unroll
                for (int j = 0; j < 4; j++) {
                    const int p = j >> 1, h = (j & 1) * 2;
                    MMA16816(acc[i][j], ah[sub][i], bh[sub][p][h], bh[sub][p][h + 1]);
                    MMA16816(acc[i][j], al[sub][i], bh[sub][p][h], bh[sub][p][h + 1]);
                    MMA16816(acc[i][j], ah[sub][i], bl[sub][p][h], bl[sub][p][h + 1]);
                }
    }

    // ---- epilogue: direct coalesced STG from accumulators (tail adds biases) ----
    asm volatile("cp.async.wait_group 0;" ::: "memory");
    const int erow = lane >> 2;          // 0..7
    const int ecol = (lane & 3) * 2;     // 0,2,4,6
    #pragma unroll
    for (int i = 0; i < 4; i++) {
        #pragma unroll
        for (int j = 0; j < 4; j++) {
            const int gm = m0 + wm * 64 + i * 16 + erow;
            const int gn = n0 + wn * 32 + j * 8 + ecol;
            float2 v0{acc[i][j][0], acc[i][j][1]};
            float2 v1{acc[i][j][2], acc[i][j][3]};
            *(float2*)(g_gates + (size_t)gm * N_G + gn) = v0;
            *(float2*)(g_gates + (size_t)(gm + 8) * N_G + gn) = v1;
        }
    }
}

// ============================================================
// 3) tail: bias + LSTM elementwise + MLP head + softmax + masked renorm
// ============================================================
__device__ __forceinline__ float sigm(float x) { return 1.0f / (1.0f + expf(-x)); }

#define OFF_H1 (NB * 9)
#define OFF_C1 (NB * 9 + NB * 128)

__global__ __launch_bounds__(128)
void tail_kernel(const float* __restrict__ c0,
                 const float* __restrict__ bih, const float* __restrict__ bhh,
                 const float* __restrict__ W1, const float* __restrict__ b1,
                 const float* __restrict__ W2, const float* __restrict__ b2,
                 const float* __restrict__ Wa, const float* __restrict__ ba,
                 const float* __restrict__ mask, float* __restrict__ out)
{
    __shared__ float W1t[128 * 65];   // [d][j], padded: conflict-free R & W
    __shared__ float Was[9 * 129];    // padded: conflict-free across 9 lanes
    __shared__ float b1s[64], b2s[128], bas[9];
    __shared__ float h1s[128], feats[64], es[128], lgs[9];

    const int t = threadIdx.x;
    for (int i = t; i < 64 * 128; i += 128) {     // coalesced read of W1 [64][128]
        int j = i >> 7, d = i & 127;
        W1t[d * 65 + j] = W1[i];
    }
    for (int i = t; i < 9 * 128; i += 128) {
        int j = i >> 7, d = i & 127;
        Was[j * 129 + d] = Wa[i];
    }
    if (t < 64) b1s[t] = b1[t];
    b2s[t] = b2[t];
    if (t < 9) bas[t] = ba[t];
    const float bi = bih[t]       + bhh[t];
    const float bf = bih[128 + t] + bhh[128 + t];
    const float bg = bih[256 + t] + bhh[256 + t];
    const float bo = bih[384 + t] + bhh[384 + t];
    __syncthreads();

    for (int r = 0; r < 8; r++) {
        const int b = blockIdx.x * 8 + r;
        const float* g = g_gates + (size_t)b * N_G;
        float ii = sigm(g[t] + bi);
        float ff = sigm(g[128 + t] + bf);
        float gg = tanhf(g[256 + t] + bg);
        float oo = sigm(g[384 + t] + bo);
        float c1 = ff * c0[(size_t)b * 128 + t] + ii * gg;
        float h1 = oo * tanhf(c1);
        out[OFF_H1 + (size_t)b * 128 + t] = h1;
        out[OFF_C1 + (size_t)b * 128 + t] = c1;
        h1s[t] = h1;
        __syncthreads();

        if (t < 64) {
            float a = b1s[t];
            #pragma unroll 8
            for (int d = 0; d < 128; d++) a += W1t[d * 65 + t] * h1s[d];
            feats[t] = fmaxf(a, 0.0f);
        }
        __syncthreads();

        {
            float a = b2s[t];
            const float* w = W2 + t * 64;   // small, L1-resident
            #pragma unroll 8
            for (int d = 0; d < 64; d++) a += w[d] * feats[d];
            es[t] = a;
        }
        __syncthreads();

        if (t < 9) {
            float a = bas[t];
            const float* w = Was + t * 129;
            #pragma unroll 8
            for (int d = 0; d < 128; d++) a += w[d] * es[d];
            lgs[t] = a;
        }
        __syncthreads();

        if (t == 0) {
            float lg[9];
            float mx = -1e30f;
            #pragma unroll
            for (int j = 0; j < 9; j++) { lg[j] = lgs[j]; mx = fmaxf(mx, lg[j]); }
            float se = 0.0f;
            #pragma unroll
            for (int j = 0; j < 9; j++) { lg[j] = expf(lg[j] - mx); se += lg[j]; }
            float inv = 1.0f / se;
            float p[9], mk[9], msum = 0.0f;
            #pragma unroll
            for (int j = 0; j < 9; j++) {
                p[j] = lg[j] * inv;
                mk[j] = p[j] * mask[(size_t)b * 9 + j];
                msum += mk[j];
            }
            if (msum > 0.0f) {
                float minv = 1.0f / msum;
                #pragma unroll
                for (int j = 0; j < 9; j++) out[(size_t)b * 9 + j] = mk[j] * minv;
            } else {
                #pragma unroll
                for (int j = 0; j < 9; j++) out[(size_t)b * 9 + j] = p[j];
            }
        }
        __syncthreads();
    }
}

// ============================================================
// launcher
// ============================================================
extern "C" void kernel_launch(void* const* d_in, const int* in_sizes, int n_in,
                              void* d_out, int out_size)
{
    const int*   ability_ids = (const int*)d_in[0];
    const int*   move_ids    = (const int*)d_in[1];
    const float* numerical   = (const float*)d_in[2];
    const float* mask        = (const float*)d_in[3];
    const float* h0          = (const float*)d_in[4];
    const float* c0          = (const float*)d_in[5];
    const float* ability_emb = (const float*)d_in[6];
    const float* move_emb    = (const float*)d_in[7];
    const float* num_W       = (const float*)d_in[8];
    const float* num_b       = (const float*)d_in[9];
    const float* Wih         = (const float*)d_in[10];
    const float* Whh         = (const float*)d_in[11];
    const float* bih         = (const float*)d_in[12];
    const float* bhh         = (const float*)d_in[13];
    const float* W1          = (const float*)d_in[14];
    const float* b1          = (const float*)d_in[15];
    const float* W2          = (const float*)d_in[16];
    const float* b2          = (const float*)d_in[17];
    const float* Wa          = (const float*)d_in[18];
    const float* ba          = (const float*)d_in[19];
    float* out = (float*)d_out;

    cudaFuncSetAttribute(gemm_kernel, cudaFuncAttributeMaxDynamicSharedMemorySize, GEMM_SMEM);
    cudaFuncSetAttribute(pack_kernel, cudaFuncAttributeMaxDynamicSharedMemorySize, EX_SMEM);

    pack_kernel<<<1240, 256, EX_SMEM>>>(ability_emb, move_emb, numerical, num_W,
                                        num_b, h0, Wih, Whh);
    gemm_kernel<<<dim3(N_G / TN, NB / TM), 128, GEMM_SMEM>>>(ability_ids, move_ids);
    tail_kernel<<<NB / 8, 128>>>(c0, bih, bhh, W1, b1, W2, b2, Wa, ba, mask, out);
}

// round 12
// speedup vs baseline: 1.2952x; 1.2952x over previous
#include <cuda_runtime.h>
#include <cuda_bf16.h>
#include <math.h>
#include <stdint.h>

#define NB     4096          // batch rows
#define K_EXT  7936          // 7808 + 128 (h0 folded in)
#define N_G    512           // 4*LSTM_HIDDEN
#define TM     128
#define TN     64
#define BK     32
#define NSTAGE 3
#define NT     (K_EXT/BK)    // 248

// ---- scratch (device globals: allocation-free rule) ----
__device__ __align__(16) __nv_bfloat16 g_eah[300 * 128];   // ability emb hi
__device__ __align__(16) __nv_bfloat16 g_eal[300 * 128];   // ability emb lo
__device__ __align__(16) __nv_bfloat16 g_emh[900 * 128];   // move emb hi
__device__ __align__(16) __nv_bfloat16 g_eml[900 * 128];   // move emb lo
__device__ __align__(16) __nv_bfloat16 g_exh[(size_t)NB * 256];  // [num | h0] hi
__device__ __align__(16) __nv_bfloat16 g_exl[(size_t)NB * 256];  // [num | h0] lo
__device__ __align__(16) __nv_bfloat16 g_wh[(size_t)N_G * K_EXT];  // W hi [N][K]
__device__ __align__(16) __nv_bfloat16 g_wl[(size_t)N_G * K_EXT];  // W lo
__device__ __align__(16) float         g_gates[(size_t)NB * N_G];  // fp32 gates (no bias)

__device__ __forceinline__ void split2(float v, __nv_bfloat16& h, __nv_bfloat16& l) {
    h = __float2bfloat16(v);
    l = __float2bfloat16(v - __bfloat162float(h));
}

// ============================================================
// 1) pack: embpack + extrapack + wpack merged (block-range dispatch)
//    blocks [0,128): extrapack (numproj + h0, 32 batch rows each)
//    blocks [128,728): embpack (2 table rows each)
//    blocks [728,1240): wpack (1 weight row each)
// ============================================================
#define EX_SMEM ((128 * 85 + 32 * 84) * 4)   // 54272 bytes

__global__ __launch_bounds__(256)
void pack_kernel(const float* __restrict__ aemb, const float* __restrict__ memb,
                 const float* __restrict__ numerical, const float* __restrict__ num_W,
                 const float* __restrict__ num_b, const float* __restrict__ h0,
                 const float* __restrict__ Wih, const float* __restrict__ Whh)
{
    const int bx = blockIdx.x;
    const int tid = threadIdx.x;

    if (bx < 128) {
        // ---- extrapack: numproj + h0 -> [B][256] bf16 hi/lo ----
        extern __shared__ float exsm[];
        float* Ws  = exsm;               // [128][85]
        float* nrs = exsm + 128 * 85;    // [32][84]
        const int m0 = bx * 32;

        for (int i = tid; i < 128 * 84; i += 256) {
            int t = i / 84, d = i - t * 84;
            Ws[t * 85 + d] = num_W[i];
        }
        for (int i = tid; i < 32 * 84; i += 256)
            nrs[i] = numerical[(size_t)m0 * 84 + i];
        __syncthreads();

        const int t = tid & 127, rbase = tid >> 7;
        const float nb = num_b[t];
        const float* w = Ws + t * 85;
        for (int rr = rbase; rr < 32; rr += 2) {
            const float* nr = nrs + rr * 84;
            float acc = nb;
            #pragma unroll 4
            for (int d = 0; d < 84; d++) acc += w[d] * nr[d];
            __nv_bfloat16 h, l;
            split2(acc, h, l);
            g_exh[(size_t)(m0 + rr) * 256 + t] = h;
            g_exl[(size_t)(m0 + rr) * 256 + t] = l;
        }
        for (int i = tid; i < 32 * 128; i += 256) {
            int r = i >> 7, d = i & 127;
            __nv_bfloat16 h, l;
            split2(h0[(size_t)(m0 + r) * 128 + d], h, l);
            g_exh[(size_t)(m0 + r) * 256 + 128 + d] = h;
            g_exl[(size_t)(m0 + r) * 256 + 128 + d] = l;
        }
    } else if (bx < 728) {
        // ---- embpack: 2 rows of the emb tables per block ----
        const int r2 = (bx - 128) * 2;
        const int r = r2 + (tid >> 7), t = tid & 127;
        __nv_bfloat16 h, l;
        if (r < 300) {
            split2(aemb[r * 128 + t], h, l);
            g_eah[r * 128 + t] = h;
            g_eal[r * 128 + t] = l;
        } else {
            int rr = r - 300;
            split2(memb[rr * 128 + t], h, l);
            g_emh[rr * 128 + t] = h;
            g_eml[rr * 128 + t] = l;
        }
    } else {
        // ---- wpack: one [Wih|Whh] row -> bf16 hi/lo ----
        const int n = bx - 728;
        for (int i4 = tid; i4 < K_EXT / 4; i4 += 256) {
            int k = i4 * 4;
            float4 v = (k < 7808) ? *(const float4*)(Wih + (size_t)n * 7808 + k)
                                  : *(const float4*)(Whh + n * 128 + (k - 7808));
            __nv_bfloat16 h0_, h1_, h2_, h3_, l0_, l1_, l2_, l3_;
            split2(v.x, h0_, l0_); split2(v.y, h1_, l1_);
            split2(v.z, h2_, l2_); split2(v.w, h3_, l3_);
            __nv_bfloat162 ph01{h0_, h1_}, ph23{h2_, h3_}, pl01{l0_, l1_}, pl23{l2_, l3_};
            uint2 uh, ul;
            uh.x = *(uint32_t*)&ph01; uh.y = *(uint32_t*)&ph23;
            ul.x = *(uint32_t*)&pl01; ul.y = *(uint32_t*)&pl23;
            size_t off = (size_t)n * K_EXT + k;
            *(uint2*)(g_wh + off) = uh;
            *(uint2*)(g_wl + off) = ul;
        }
    }
}

// ============================================================
// 2) GEMM: gates[4096][512] = x @ W^T (3-term bf16 split)
//    EXACT R10 config (proven 368.6us): CTA 128x64, 256 thr, warp 32x32,
//    BK=32, cp.async 3-stage, ldmatrix + mma.sync.m16n8k16.
// ============================================================
#define LDP 40                          // padded leading dim (elements)
#define A_STAGE_B (TM * LDP * 2)        // 10240 bytes per (hi|lo)
#define B_STAGE_B (TN * LDP * 2)        // 5120 bytes per (hi|lo)
#define OFF_AL    (A_STAGE_B)           // 10240
#define OFF_BH    (2 * A_STAGE_B)       // 20480
#define OFF_BL    (2 * A_STAGE_B + B_STAGE_B)  // 25600
#define STAGE_B   (2 * A_STAGE_B + 2 * B_STAGE_B)  // 30720
#define IDS_B     (128 * 60 * 2)        // 15360 (u16 id table)
#define SM_STG    IDS_B
#define GEMM_SMEM (IDS_B + NSTAGE * STAGE_B)   // 107520

__device__ __forceinline__ uint32_t smem_u32(const void* p) {
    uint32_t a;
    asm("{ .reg .u64 t; cvta.to.shared.u64 t, %1; cvt.u32.u64 %0, t; }" : "=r"(a) : "l"(p));
    return a;
}
__device__ __forceinline__ void cp16(uint32_t s, const void* g) {
    asm volatile("cp.async.cg.shared.global [%0], [%1], 16;" :: "r"(s), "l"(g));
}
#define LDSM4(r, addr) \
    asm volatile("ldmatrix.sync.aligned.m8n8.x4.shared.b16 {%0,%1,%2,%3}, [%4];" \
        : "=r"((r)[0]), "=r"((r)[1]), "=r"((r)[2]), "=r"((r)[3]) : "r"(addr))
#define MMA16816(c, a, b0, b1) \
    asm volatile("mma.sync.aligned.m16n8k16.row.col.f32.bf16.bf16.f32 " \
        "{%0,%1,%2,%3}, {%4,%5,%6,%7}, {%8,%9}, {%0,%1,%2,%3};" \
        : "+f"((c)[0]), "+f"((c)[1]), "+f"((c)[2]), "+f"((c)[3]) \
        : "r"((a)[0]), "r"((a)[1]), "r"((a)[2]), "r"((a)[3]), "r"(b0), "r"(b1))

__global__ __launch_bounds__(256, 2)
void gemm_kernel(const int* __restrict__ aid, const int* __restrict__ mid)
{
    extern __shared__ char smbase[];
    const uint32_t sb = smem_u32(smbase);
    const int tid = threadIdx.x;
    const int n0 = blockIdx.x * TN;
    const int m0 = blockIdx.y * TM;

    // ---- load id table: sid[r][0..11]=ability, sid[r][12..59]=move ----
    uint16_t* sid = (uint16_t*)smbase;
    {
        const int* asrc = aid + (size_t)m0 * 12;     // 1536 contiguous ints
        const int* msrc = mid + (size_t)m0 * 48;     // 6144 contiguous ints
        for (int i = tid; i < 1536; i += 256) {
            int r = i / 12, s = i % 12;
            sid[r * 60 + s] = (uint16_t)asrc[i];
        }
        for (int i = tid; i < 6144; i += 256) {
            int r = i / 48, s = i % 48;
            sid[r * 60 + 12 + s] = (uint16_t)msrc[i];
        }
    }
    __syncthreads();

    // ---- per-thread cp.async roles: A rows r0, r0+64 (hi+lo), B row r0, chunk c ----
    const int r0 = tid >> 2;             // 0..63
    const int r1 = r0 + 64;
    const int c  = tid & 3;              // 16B chunk within 64B k-row
    const uint32_t soff_a0h = r0 * (LDP * 2) + c * 16;
    const uint32_t soff_a1h = r1 * (LDP * 2) + c * 16;
    const uint32_t soff_a0l = OFF_AL + r0 * (LDP * 2) + c * 16;
    const uint32_t soff_a1l = OFF_AL + r1 * (LDP * 2) + c * 16;
    const uint32_t soff_bh  = OFF_BH + r0 * (LDP * 2) + c * 16;
    const uint32_t soff_bl  = OFF_BL + r0 * (LDP * 2) + c * 16;
    const char* bsrc_h = (const char*)(g_wh + (size_t)(n0 + r0) * K_EXT) + c * 16;
    const char* bsrc_l = (const char*)(g_wl + (size_t)(n0 + r0) * K_EXT) + c * 16;

    auto prefetch = [&](int ss, int buf) {
        const uint32_t dst = sb + SM_STG + buf * STAGE_B;
        const int k = ss * BK + c * 8;
        const char *a0h, *a1h, *a0l, *a1l;
        if (k < 7680) {
            const int s = k >> 7, d = k & 127;
            const int id0 = sid[r0 * 60 + s];
            const int id1 = sid[r1 * 60 + s];
            if (s < 12) {
                a0h = (const char*)(g_eah + id0 * 128 + d);
                a0l = (const char*)(g_eal + id0 * 128 + d);
                a1h = (const char*)(g_eah + id1 * 128 + d);
                a1l = (const char*)(g_eal + id1 * 128 + d);
            } else {
                a0h = (const char*)(g_emh + id0 * 128 + d);
                a0l = (const char*)(g_eml + id0 * 128 + d);
                a1h = (const char*)(g_emh + id1 * 128 + d);
                a1l = (const char*)(g_eml + id1 * 128 + d);
            }
        } else {
            const int d = k - 7680;
            a0h = (const char*)(g_exh + (size_t)(m0 + r0) * 256 + d);
            a0l = (const char*)(g_exl + (size_t)(m0 + r0) * 256 + d);
            a1h = (const char*)(g_exh + (size_t)(m0 + r1) * 256 + d);
            a1l = (const char*)(g_exl + (size_t)(m0 + r1) * 256 + d);
        }
        cp16(dst + soff_a0h, a0h);
        cp16(dst + soff_a1h, a1h);
        cp16(dst + soff_a0l, a0l);
        cp16(dst + soff_a1l, a1l);
        cp16(dst + soff_bh, bsrc_h + (size_t)ss * (BK * 2));
        cp16(dst + soff_bl, bsrc_l + (size_t)ss * (BK * 2));
        asm volatile("cp.async.commit_group;" ::: "memory");
    };

    const int wid = tid >> 5;
    const int lane = tid & 31;
    const int wm = wid & 3;              // 4 warps along M (32 rows each)
    const int wn = wid >> 2;             // 2 warps along N (32 cols each)

    // ---- ldmatrix lane-address element offsets (within stage, in elements) ----
    const int arow = lane & 15;
    const int akh  = (lane >> 4) << 3;
    int aoff[2];
    #pragma unroll
    for (int i = 0; i < 2; i++)
        aoff[i] = (wm * 32 + i * 16 + arow) * LDP + akh;
    const int bn  = (lane & 7) + ((lane >> 4) << 3);
    const int bkh = ((lane >> 3) & 1) << 3;
    int boff[2];
    #pragma unroll
    for (int p = 0; p < 2; p++)
        boff[p] = (wn * 32 + p * 16 + bn) * LDP + bkh;

    float acc[2][4][4];   // [m-tile][n8-tile][frag]
    #pragma unroll
    for (int i = 0; i < 2; i++)
        #pragma unroll
        for (int j = 0; j < 4; j++)
            #pragma unroll
            for (int q = 0; q < 4; q++) acc[i][j][q] = 0.0f;

    // ---- prologue: stages 0,1 in flight ----
    prefetch(0, 0);
    prefetch(1, 1);

    #pragma unroll 1
    for (int t = 0; t < NT; ++t) {
        asm volatile("cp.async.wait_group 1;" ::: "memory");
        __syncthreads();   // stage t visible; all warps done with stage t-1

        if (t + 2 < NT) {
            prefetch(t + 2, (t + 2) % NSTAGE);
        } else {
            asm volatile("cp.async.commit_group;" ::: "memory");  // keep group count uniform
        }

        const uint32_t stg_u = sb + SM_STG + (t % NSTAGE) * STAGE_B;
        const uint32_t Ah_u = stg_u;
        const uint32_t Al_u = stg_u + OFF_AL;
        const uint32_t Bh_u = stg_u + OFF_BH;
        const uint32_t Bl_u = stg_u + OFF_BL;

        #pragma unroll
        for (int sub = 0; sub < 2; sub++) {
            const int k16 = sub * 16;
            uint32_t ah[2][4], al[2][4], bh[2][4], bl[2][4];
            // 8 independent LDSM.x4 up front (MLP)
            #pragma unroll
            for (int i = 0; i < 2; i++) {
                LDSM4(ah[i], Ah_u + (uint32_t)(aoff[i] + k16) * 2);
                LDSM4(al[i], Al_u + (uint32_t)(aoff[i] + k16) * 2);
            }
            #pragma unroll
            for (int p = 0; p < 2; p++) {
                LDSM4(bh[p], Bh_u + (uint32_t)(boff[p] + k16) * 2);
                LDSM4(bl[p], Bl_u + (uint32_t)(boff[p] + k16) * 2);
            }
            // 24 mmas across 8 independent accumulator tiles
            #pragma unroll
            for (int i = 0; i < 2; i++)
                #pragma unroll
                for (int j = 0; j < 4; j++) {
                    const int p = j >> 1, h = (j & 1) * 2;
                    MMA16816(acc[i][j], ah[i], bh[p][h], bh[p][h + 1]);
                    MMA16816(acc[i][j], al[i], bh[p][h], bh[p][h + 1]);
                    MMA16816(acc[i][j], ah[i], bl[p][h], bl[p][h + 1]);
                }
        }
    }

    // ---- epilogue: direct coalesced STG from accumulators (tail adds biases) ----
    asm volatile("cp.async.wait_group 0;" ::: "memory");
    const int erow = lane >> 2;          // 0..7
    const int ecol = (lane & 3) * 2;     // 0,2,4,6
    #pragma unroll
    for (int i = 0; i < 2; i++) {
        #pragma unroll
        for (int j = 0; j < 4; j++) {
            const int gm = m0 + wm * 32 + i * 16 + erow;
            const int gn = n0 + wn * 32 + j * 8 + ecol;
            float2 v0{acc[i][j][0], acc[i][j][1]};
            float2 v1{acc[i][j][2], acc[i][j][3]};
            *(float2*)(g_gates + (size_t)gm * N_G + gn) = v0;
            *(float2*)(g_gates + (size_t)(gm + 8) * N_G + gn) = v1;
        }
    }
}

// ============================================================
// 3) tail: bias + LSTM elementwise + MLP head + softmax + masked renorm.
//    256 threads: two 128-lane groups process 2 rows concurrently
//    (halves the barrier-chain length per block vs 128-thread version).
// ============================================================
__device__ __forceinline__ float sigm(float x) { return 1.0f / (1.0f + expf(-x)); }

#define OFF_H1 (NB * 9)
#define OFF_C1 (NB * 9 + NB * 128)

__global__ __launch_bounds__(256)
void tail_kernel(const float* __restrict__ c0,
                 const float* __restrict__ bih, const float* __restrict__ bhh,
                 const float* __restrict__ W1, const float* __restrict__ b1,
                 const float* __restrict__ W2, const float* __restrict__ b2,
                 const float* __restrict__ Wa, const float* __restrict__ ba,
                 const float* __restrict__ mask, float* __restrict__ out)
{
    __shared__ float W1t[128 * 65];   // [d][j], padded: conflict-free R & W
    __shared__ float Was[9 * 129];    // padded: conflict-free across 9 lanes
    __shared__ float b1s[64], b2s[128], bas[9];
    __shared__ float h1s[2][128], feats[2][66], es[2][128], lgs[2][9];

    const int tid = threadIdx.x;
    const int gg_ = tid >> 7;         // row-in-pair (0/1)
    const int t = tid & 127;
    for (int i = tid; i < 64 * 128; i += 256) {   // coalesced read of W1 [64][128]
        int j = i >> 7, d = i & 127;
        W1t[d * 65 + j] = W1[i];
    }
    for (int i = tid; i < 9 * 128; i += 256) {
        int j = i >> 7, d = i & 127;
        Was[j * 129 + d] = Wa[i];
    }
    if (tid < 64) b1s[tid] = b1[tid];
    if (tid < 128) b2s[tid] = b2[tid];
    if (tid < 9) bas[tid] = ba[tid];
    const float bi = bih[t]       + bhh[t];
    const float bf = bih[128 + t] + bhh[128 + t];
    const float bg = bih[256 + t] + bhh[256 + t];
    const float bo = bih[384 + t] + bhh[384 + t];
    __syncthreads();

    for (int r = 0; r < 4; r++) {
        const int b = blockIdx.x * 8 + r * 2 + gg_;
        const float* g = g_gates + (size_t)b * N_G;
        float ii = sigm(g[t] + bi);
        float ff = sigm(g[128 + t] + bf);
        float gv = tanhf(g[256 + t] + bg);
        float oo = sigm(g[384 + t] + bo);
        float c1 = ff * c0[(size_t)b * 128 + t] + ii * gv;
        float h1 = oo * tanhf(c1);
        out[OFF_H1 + (size_t)b * 128 + t] = h1;
        out[OFF_C1 + (size_t)b * 128 + t] = c1;
        h1s[gg_][t] = h1;
        __syncthreads();

        if (t < 64) {
            float a = b1s[t];
            #pragma unroll 8
            for (int d = 0; d < 128; d++) a += W1t[d * 65 + t] * h1s[gg_][d];
            feats[gg_][t] = fmaxf(a, 0.0f);
        }
        __syncthreads();

        {
            float a = b2s[t];
            const float* w = W2 + t * 64;   // small, L1-resident
            #pragma unroll 8
            for (int d = 0; d < 64; d++) a += w[d] * feats[gg_][d];
            es[gg_][t] = a;
        }
        __syncthreads();

        if (t < 9) {
            float a = bas[t];
            const float* w = Was + t * 129;
            #pragma unroll 8
            for (int d = 0; d < 128; d++) a += w[d] * es[gg_][d];
            lgs[gg_][t] = a;
        }
        __syncthreads();

        if (t == 0) {
            float lg[9];
            float mx = -1e30f;
            #pragma unroll
            for (int j = 0; j < 9; j++) { lg[j] = lgs[gg_][j]; mx = fmaxf(mx, lg[j]); }
            float se = 0.0f;
            #pragma unroll
            for (int j = 0; j < 9; j++) { lg[j] = expf(lg[j] - mx); se += lg[j]; }
            float inv = 1.0f / se;
            float p[9], mk[9], msum = 0.0f;
            #pragma unroll
            for (int j = 0; j < 9; j++) {
                p[j] = lg[j] * inv;
                mk[j] = p[j] * mask[(size_t)b * 9 + j];
                msum += mk[j];
            }
            if (msum > 0.0f) {
                float minv = 1.0f / msum;
                #pragma unroll
                for (int j = 0; j < 9; j++) out[(size_t)b * 9 + j] = mk[j] * minv;
            } else {
                #pragma unroll
                for (int j = 0; j < 9; j++) out[(size_t)b * 9 + j] = p[j];
            }
        }
        __syncthreads();
    }
}

// ============================================================
// launcher
// ============================================================
extern "C" void kernel_launch(void* const* d_in, const int* in_sizes, int n_in,
                              void* d_out, int out_size)
{
    const int*   ability_ids = (const int*)d_in[0];
    const int*   move_ids    = (const int*)d_in[1];
    const float* numerical   = (const float*)d_in[2];
    const float* mask        = (const float*)d_in[3];
    const float* h0          = (const float*)d_in[4];
    const float* c0          = (const float*)d_in[5];
    const float* ability_emb = (const float*)d_in[6];
    const float* move_emb    = (const float*)d_in[7];
    const float* num_W       = (const float*)d_in[8];
    const float* num_b       = (const float*)d_in[9];
    const float* Wih         = (const float*)d_in[10];
    const float* Whh         = (const float*)d_in[11];
    const float* bih         = (const float*)d_in[12];
    const float* bhh         = (const float*)d_in[13];
    const float* W1          = (const float*)d_in[14];
    const float* b1          = (const float*)d_in[15];
    const float* W2          = (const float*)d_in[16];
    const float* b2          = (const float*)d_in[17];
    const float* Wa          = (const float*)d_in[18];
    const float* ba          = (const float*)d_in[19];
    float* out = (float*)d_out;

    cudaFuncSetAttribute(gemm_kernel, cudaFuncAttributeMaxDynamicSharedMemorySize, GEMM_SMEM);
    cudaFuncSetAttribute(pack_kernel, cudaFuncAttributeMaxDynamicSharedMemorySize, EX_SMEM);

    pack_kernel<<<1240, 256, EX_SMEM>>>(ability_emb, move_emb, numerical, num_W,
                                        num_b, h0, Wih, Whh);
    gemm_kernel<<<dim3(N_G / TN, NB / TM), 256, GEMM_SMEM>>>(ability_ids, move_ids);
    tail_kernel<<<NB / 8, 256>>>(c0, bih, bhh, W1, b1, W2, b2, Wa, ba, mask, out);
}

// round 13
// speedup vs baseline: 1.6540x; 1.2771x over previous
#include <cuda_runtime.h>
#include <cuda_bf16.h>
#include <math.h>
#include <stdint.h>

#define NB     4096          // batch rows
#define K_EXT  7936          // 7808 + 128 (h0 folded in)
#define N_G    512           // 4*LSTM_HIDDEN
#define TM     128
#define TN     64
#define BK     32
#define NSTAGE 3
#define NT     (K_EXT/BK)    // 248

// ---- scratch (device globals: allocation-free rule) ----
__device__ __align__(16) __nv_bfloat16 g_eah[300 * 128];   // ability emb hi
__device__ __align__(16) __nv_bfloat16 g_eal[300 * 128];   // ability emb lo
__device__ __align__(16) __nv_bfloat16 g_emh[900 * 128];   // move emb hi
__device__ __align__(16) __nv_bfloat16 g_eml[900 * 128];   // move emb lo
__device__ __align__(16) __nv_bfloat16 g_exh[(size_t)NB * 256];  // [num | h0] hi
__device__ __align__(16) __nv_bfloat16 g_exl[(size_t)NB * 256];  // [num | h0] lo
__device__ __align__(16) __nv_bfloat16 g_wh[(size_t)N_G * K_EXT];  // W hi [N][K]
__device__ __align__(16) __nv_bfloat16 g_wl[(size_t)N_G * K_EXT];  // W lo
__device__ __align__(16) float         g_gates[(size_t)NB * N_G];  // fp32 gates (no bias)

__device__ __forceinline__ void split2(float v, __nv_bfloat16& h, __nv_bfloat16& l) {
    h = __float2bfloat16(v);
    l = __float2bfloat16(v - __bfloat162float(h));
}

// ============================================================
// 1a) pack_stream: embpack + wpack, NO dynamic smem (occupancy uncapped)
//     blocks [0,600): embpack (2 table rows each)
//     blocks [600,1112): wpack (1 weight row each)
// ============================================================
__global__ __launch_bounds__(256)
void pack_stream_kernel(const float* __restrict__ aemb, const float* __restrict__ memb,
                        const float* __restrict__ Wih, const float* __restrict__ Whh)
{
    const int bx = blockIdx.x;
    const int tid = threadIdx.x;

    if (bx < 600) {
        // ---- embpack: 2 rows of the emb tables per block ----
        const int r = bx * 2 + (tid >> 7), t = tid & 127;
        __nv_bfloat16 h, l;
        if (r < 300) {
            split2(aemb[r * 128 + t], h, l);
            g_eah[r * 128 + t] = h;
            g_eal[r * 128 + t] = l;
        } else {
            int rr = r - 300;
            split2(memb[rr * 128 + t], h, l);
            g_emh[rr * 128 + t] = h;
            g_eml[rr * 128 + t] = l;
        }
    } else {
        // ---- wpack: one [Wih|Whh] row -> bf16 hi/lo ----
        const int n = bx - 600;
        for (int i4 = tid; i4 < K_EXT / 4; i4 += 256) {
            int k = i4 * 4;
            float4 v = (k < 7808) ? *(const float4*)(Wih + (size_t)n * 7808 + k)
                                  : *(const float4*)(Whh + n * 128 + (k - 7808));
            __nv_bfloat16 h0_, h1_, h2_, h3_, l0_, l1_, l2_, l3_;
            split2(v.x, h0_, l0_); split2(v.y, h1_, l1_);
            split2(v.z, h2_, l2_); split2(v.w, h3_, l3_);
            __nv_bfloat162 ph01{h0_, h1_}, ph23{h2_, h3_}, pl01{l0_, l1_}, pl23{l2_, l3_};
            uint2 uh, ul;
            uh.x = *(uint32_t*)&ph01; uh.y = *(uint32_t*)&ph23;
            ul.x = *(uint32_t*)&pl01; ul.y = *(uint32_t*)&pl23;
            size_t off = (size_t)n * K_EXT + k;
            *(uint2*)(g_wh + off) = uh;
            *(uint2*)(g_wl + off) = ul;
        }
    }
}

// ============================================================
// 1b) pack_extra: numproj + h0 -> [B][256] bf16 hi/lo (needs 54KB smem)
// ============================================================
#define EX_SMEM ((128 * 85 + 32 * 84) * 4)   // 54272 bytes

__global__ __launch_bounds__(256)
void pack_extra_kernel(const float* __restrict__ numerical, const float* __restrict__ num_W,
                       const float* __restrict__ num_b, const float* __restrict__ h0)
{
    extern __shared__ float exsm[];
    float* Ws  = exsm;               // [128][85]
    float* nrs = exsm + 128 * 85;    // [32][84]
    const int tid = threadIdx.x;
    const int m0 = blockIdx.x * 32;

    for (int i = tid; i < 128 * 84; i += 256) {
        int t = i / 84, d = i - t * 84;
        Ws[t * 85 + d] = num_W[i];
    }
    for (int i = tid; i < 32 * 84; i += 256)
        nrs[i] = numerical[(size_t)m0 * 84 + i];
    __syncthreads();

    const int t = tid & 127, rbase = tid >> 7;
    const float nb = num_b[t];
    const float* w = Ws + t * 85;
    for (int rr = rbase; rr < 32; rr += 2) {
        const float* nr = nrs + rr * 84;
        float acc = nb;
        #pragma unroll 4
        for (int d = 0; d < 84; d++) acc += w[d] * nr[d];
        __nv_bfloat16 h, l;
        split2(acc, h, l);
        g_exh[(size_t)(m0 + rr) * 256 + t] = h;
        g_exl[(size_t)(m0 + rr) * 256 + t] = l;
    }
    for (int i = tid; i < 32 * 128; i += 256) {
        int r = i >> 7, d = i & 127;
        __nv_bfloat16 h, l;
        split2(h0[(size_t)(m0 + r) * 128 + d], h, l);
        g_exh[(size_t)(m0 + r) * 256 + 128 + d] = h;
        g_exl[(size_t)(m0 + r) * 256 + 128 + d] = l;
    }
}

// ============================================================
// 2) GEMM: gates[4096][512] = x @ W^T (3-term bf16 split)
//    EXACT R10 config (proven 368.6us): CTA 128x64, 256 thr, warp 32x32,
//    BK=32, cp.async 3-stage, ldmatrix + mma.sync.m16n8k16.
// ============================================================
#define LDP 40                          // padded leading dim (elements)
#define A_STAGE_B (TM * LDP * 2)        // 10240 bytes per (hi|lo)
#define B_STAGE_B (TN * LDP * 2)        // 5120 bytes per (hi|lo)
#define OFF_AL    (A_STAGE_B)           // 10240
#define OFF_BH    (2 * A_STAGE_B)       // 20480
#define OFF_BL    (2 * A_STAGE_B + B_STAGE_B)  // 25600
#define STAGE_B   (2 * A_STAGE_B + 2 * B_STAGE_B)  // 30720
#define IDS_B     (128 * 60 * 2)        // 15360 (u16 id table)
#define SM_STG    IDS_B
#define GEMM_SMEM (IDS_B + NSTAGE * STAGE_B)   // 107520

__device__ __forceinline__ uint32_t smem_u32(const void* p) {
    uint32_t a;
    asm("{ .reg .u64 t; cvta.to.shared.u64 t, %1; cvt.u32.u64 %0, t; }" : "=r"(a) : "l"(p));
    return a;
}
__device__ __forceinline__ void cp16(uint32_t s, const void* g) {
    asm volatile("cp.async.cg.shared.global [%0], [%1], 16;" :: "r"(s), "l"(g));
}
#define LDSM4(r, addr) \
    asm volatile("ldmatrix.sync.aligned.m8n8.x4.shared.b16 {%0,%1,%2,%3}, [%4];" \
        : "=r"((r)[0]), "=r"((r)[1]), "=r"((r)[2]), "=r"((r)[3]) : "r"(addr))
#define MMA16816(c, a, b0, b1) \
    asm volatile("mma.sync.aligned.m16n8k16.row.col.f32.bf16.bf16.f32 " \
        "{%0,%1,%2,%3}, {%4,%5,%6,%7}, {%8,%9}, {%0,%1,%2,%3};" \
        : "+f"((c)[0]), "+f"((c)[1]), "+f"((c)[2]), "+f"((c)[3]) \
        : "r"((a)[0]), "r"((a)[1]), "r"((a)[2]), "r"((a)[3]), "r"(b0), "r"(b1))

__global__ __launch_bounds__(256, 2)
void gemm_kernel(const int* __restrict__ aid, const int* __restrict__ mid)
{
    extern __shared__ char smbase[];
    const uint32_t sb = smem_u32(smbase);
    const int tid = threadIdx.x;
    const int n0 = blockIdx.x * TN;
    const int m0 = blockIdx.y * TM;

    // ---- load id table: sid[r][0..11]=ability, sid[r][12..59]=move ----
    uint16_t* sid = (uint16_t*)smbase;
    {
        const int* asrc = aid + (size_t)m0 * 12;     // 1536 contiguous ints
        const int* msrc = mid + (size_t)m0 * 48;     // 6144 contiguous ints
        for (int i = tid; i < 1536; i += 256) {
            int r = i / 12, s = i % 12;
            sid[r * 60 + s] = (uint16_t)asrc[i];
        }
        for (int i = tid; i < 6144; i += 256) {
            int r = i / 48, s = i % 48;
            sid[r * 60 + 12 + s] = (uint16_t)msrc[i];
        }
    }
    __syncthreads();

    // ---- per-thread cp.async roles: A rows r0, r0+64 (hi+lo), B row r0, chunk c ----
    const int r0 = tid >> 2;             // 0..63
    const int r1 = r0 + 64;
    const int c  = tid & 3;              // 16B chunk within 64B k-row
    const uint32_t soff_a0h = r0 * (LDP * 2) + c * 16;
    const uint32_t soff_a1h = r1 * (LDP * 2) + c * 16;
    const uint32_t soff_a0l = OFF_AL + r0 * (LDP * 2) + c * 16;
    const uint32_t soff_a1l = OFF_AL + r1 * (LDP * 2) + c * 16;
    const uint32_t soff_bh  = OFF_BH + r0 * (LDP * 2) + c * 16;
    const uint32_t soff_bl  = OFF_BL + r0 * (LDP * 2) + c * 16;
    const char* bsrc_h = (const char*)(g_wh + (size_t)(n0 + r0) * K_EXT) + c * 16;
    const char* bsrc_l = (const char*)(g_wl + (size_t)(n0 + r0) * K_EXT) + c * 16;

    auto prefetch = [&](int ss, int buf) {
        const uint32_t dst = sb + SM_STG + buf * STAGE_B;
        const int k = ss * BK + c * 8;
        const char *a0h, *a1h, *a0l, *a1l;
        if (k < 7680) {
            const int s = k >> 7, d = k & 127;
            const int id0 = sid[r0 * 60 + s];
            const int id1 = sid[r1 * 60 + s];
            if (s < 12) {
                a0h = (const char*)(g_eah + id0 * 128 + d);
                a0l = (const char*)(g_eal + id0 * 128 + d);
                a1h = (const char*)(g_eah + id1 * 128 + d);
                a1l = (const char*)(g_eal + id1 * 128 + d);
            } else {
                a0h = (const char*)(g_emh + id0 * 128 + d);
                a0l = (const char*)(g_eml + id0 * 128 + d);
                a1h = (const char*)(g_emh + id1 * 128 + d);
                a1l = (const char*)(g_eml + id1 * 128 + d);
            }
        } else {
            const int d = k - 7680;
            a0h = (const char*)(g_exh + (size_t)(m0 + r0) * 256 + d);
            a0l = (const char*)(g_exl + (size_t)(m0 + r0) * 256 + d);
            a1h = (const char*)(g_exh + (size_t)(m0 + r1) * 256 + d);
            a1l = (const char*)(g_exl + (size_t)(m0 + r1) * 256 + d);
        }
        cp16(dst + soff_a0h, a0h);
        cp16(dst + soff_a1h, a1h);
        cp16(dst + soff_a0l, a0l);
        cp16(dst + soff_a1l, a1l);
        cp16(dst + soff_bh, bsrc_h + (size_t)ss * (BK * 2));
        cp16(dst + soff_bl, bsrc_l + (size_t)ss * (BK * 2));
        asm volatile("cp.async.commit_group;" ::: "memory");
    };

    const int wid = tid >> 5;
    const int lane = tid & 31;
    const int wm = wid & 3;              // 4 warps along M (32 rows each)
    const int wn = wid >> 2;             // 2 warps along N (32 cols each)

    // ---- ldmatrix lane-address element offsets (within stage, in elements) ----
    const int arow = lane & 15;
    const int akh  = (lane >> 4) << 3;
    int aoff[2];
    #pragma unroll
    for (int i = 0; i < 2; i++)
        aoff[i] = (wm * 32 + i * 16 + arow) * LDP + akh;
    const int bn  = (lane & 7) + ((lane >> 4) << 3);
    const int bkh = ((lane >> 3) & 1) << 3;
    int boff[2];
    #pragma unroll
    for (int p = 0; p < 2; p++)
        boff[p] = (wn * 32 + p * 16 + bn) * LDP + bkh;

    float acc[2][4][4];   // [m-tile][n8-tile][frag]
    #pragma unroll
    for (int i = 0; i < 2; i++)
        #pragma unroll
        for (int j = 0; j < 4; j++)
            #pragma unroll
            for (int q = 0; q < 4; q++) acc[i][j][q] = 0.0f;

    // ---- prologue: stages 0,1 in flight ----
    prefetch(0, 0);
    prefetch(1, 1);

    #pragma unroll 1
    for (int t = 0; t < NT; ++t) {
        asm volatile("cp.async.wait_group 1;" ::: "memory");
        __syncthreads();   // stage t visible; all warps done with stage t-1

        if (t + 2 < NT) {
            prefetch(t + 2, (t + 2) % NSTAGE);
        } else {
            asm volatile("cp.async.commit_group;" ::: "memory");  // keep group count uniform
        }

        const uint32_t stg_u = sb + SM_STG + (t % NSTAGE) * STAGE_B;
        const uint32_t Ah_u = stg_u;
        const uint32_t Al_u = stg_u + OFF_AL;
        const uint32_t Bh_u = stg_u + OFF_BH;
        const uint32_t Bl_u = stg_u + OFF_BL;

        #pragma unroll
        for (int sub = 0; sub < 2; sub++) {
            const int k16 = sub * 16;
            uint32_t ah[2][4], al[2][4], bh[2][4], bl[2][4];
            // 8 independent LDSM.x4 up front (MLP)
            #pragma unroll
            for (int i = 0; i < 2; i++) {
                LDSM4(ah[i], Ah_u + (uint32_t)(aoff[i] + k16) * 2);
                LDSM4(al[i], Al_u + (uint32_t)(aoff[i] + k16) * 2);
            }
            #pragma unroll
            for (int p = 0; p < 2; p++) {
                LDSM4(bh[p], Bh_u + (uint32_t)(boff[p] + k16) * 2);
                LDSM4(bl[p], Bl_u + (uint32_t)(boff[p] + k16) * 2);
            }
            // 24 mmas across 8 independent accumulator tiles
            #pragma unroll
            for (int i = 0; i < 2; i++)
                #pragma unroll
                for (int j = 0; j < 4; j++) {
                    const int p = j >> 1, h = (j & 1) * 2;
                    MMA16816(acc[i][j], ah[i], bh[p][h], bh[p][h + 1]);
                    MMA16816(acc[i][j], al[i], bh[p][h], bh[p][h + 1]);
                    MMA16816(acc[i][j], ah[i], bl[p][h], bl[p][h + 1]);
                }
        }
    }

    // ---- epilogue: direct coalesced STG from accumulators (tail adds biases) ----
    asm volatile("cp.async.wait_group 0;" ::: "memory");
    const int erow = lane >> 2;          // 0..7
    const int ecol = (lane & 3) * 2;     // 0,2,4,6
    #pragma unroll
    for (int i = 0; i < 2; i++) {
        #pragma unroll
        for (int j = 0; j < 4; j++) {
            const int gm = m0 + wm * 32 + i * 16 + erow;
            const int gn = n0 + wn * 32 + j * 8 + ecol;
            float2 v0{acc[i][j][0], acc[i][j][1]};
            float2 v1{acc[i][j][2], acc[i][j][3]};
            *(float2*)(g_gates + (size_t)gm * N_G + gn) = v0;
            *(float2*)(g_gates + (size_t)(gm + 8) * N_G + gn) = v1;
        }
    }
}

// ============================================================
// 3) tail: 8 rows per block, ALL rows processed in parallel per phase.
//    5 barriers total per block (vs 20 in the looped version).
//    W1/W2/Wa staged transposed+padded in smem (conflict-free).
// ============================================================
__device__ __forceinline__ float sigm(float x) { return 1.0f / (1.0f + expf(-x)); }

#define OFF_H1 (NB * 9)
#define OFF_C1 (NB * 9 + NB * 128)

// dynamic smem float offsets
#define T_W1T   0                          // [128][65]
#define T_W2T   (T_W1T + 128 * 65)         // [64][129]
#define T_WAS   (T_W2T + 64 * 129)         // [9][129]
#define T_BSUM  (T_WAS + 9 * 129)          // [512]
#define T_B1    (T_BSUM + 512)             // [64]
#define T_B2    (T_B1 + 64)                // [128]
#define T_BA    (T_B2 + 128)               // [12]
#define T_H1S   (T_BA + 12)                // [8][132]
#define T_FE    (T_H1S + 8 * 132)          // [8][68]
#define T_ES    (T_FE + 8 * 68)            // [8][132]
#define T_LG    (T_ES + 8 * 132)           // [8][12]
#define T_TOT   (T_LG + 8 * 12)
#define TAIL_SMEM (T_TOT * 4)              // ~84.9 KB

__global__ __launch_bounds__(256)
void tail_kernel(const float* __restrict__ c0,
                 const float* __restrict__ bih, const float* __restrict__ bhh,
                 const float* __restrict__ W1, const float* __restrict__ b1,
                 const float* __restrict__ W2, const float* __restrict__ b2,
                 const float* __restrict__ Wa, const float* __restrict__ ba,
                 const float* __restrict__ mask, float* __restrict__ out)
{
    extern __shared__ float sm[];
    float* W1t  = sm + T_W1T;    // [d][j] stride 65
    float* W2t  = sm + T_W2T;    // [d][t] stride 129
    float* Was  = sm + T_WAS;    // [j][d] stride 129
    float* bsum = sm + T_BSUM;
    float* b1s  = sm + T_B1;
    float* b2s  = sm + T_B2;
    float* bas  = sm + T_BA;
    float* h1s  = sm + T_H1S;    // [r][t] stride 132
    float* fes  = sm + T_FE;     // [r][j] stride 68
    float* es   = sm + T_ES;     // [r][t] stride 132
    float* lgs  = sm + T_LG;     // [r][j] stride 12

    const int tid = threadIdx.x;
    const int b0 = blockIdx.x * 8;

    // ---- stage weights/biases (all coalesced reads) ----
    for (int i = tid; i < 64 * 128; i += 256) {   // W1 [64][128]
        int j = i >> 7, d = i & 127;
        W1t[d * 65 + j] = W1[i];
    }
    for (int i = tid; i < 128 * 64; i += 256) {   // W2 [128][64]
        int t = i >> 6, d = i & 63;
        W2t[d * 129 + t] = W2[i];
    }
    for (int i = tid; i < 9 * 128; i += 256) {    // Wa [9][128]
        int j = i >> 7, d = i & 127;
        Was[j * 129 + d] = Wa[i];
    }
    for (int i = tid; i < 512; i += 256) bsum[i] = bih[i] + bhh[i];
    if (tid < 64) b1s[tid] = b1[tid];
    if (tid < 128) b2s[tid] = b2[tid];
    if (tid < 9) bas[tid] = ba[tid];
    __syncthreads();

    // ---- phase 1: LSTM elementwise, 8 rows x 128 = 1024 items ----
    #pragma unroll
    for (int p = 0; p < 4; p++) {
        const int idx = p * 256 + tid;
        const int r = idx >> 7, t = idx & 127;
        const int b = b0 + r;
        const float* g = g_gates + (size_t)b * N_G;
        float ii = sigm(g[t] + bsum[t]);
        float ff = sigm(g[128 + t] + bsum[128 + t]);
        float gv = tanhf(g[256 + t] + bsum[256 + t]);
        float oo = sigm(g[384 + t] + bsum[384 + t]);
        float c1 = ff * c0[(size_t)b * 128 + t] + ii * gv;
        float h1 = oo * tanhf(c1);
        out[OFF_H1 + (size_t)b * 128 + t] = h1;
        out[OFF_C1 + (size_t)b * 128 + t] = c1;
        h1s[r * 132 + t] = h1;
    }
    __syncthreads();

    // ---- phase 2: feat = relu(h1 @ W1^T + b1), 8 x 64 = 512 items ----
    #pragma unroll
    for (int p = 0; p < 2; p++) {
        const int idx = p * 256 + tid;
        const int r = idx >> 6, j = idx & 63;
        float a = b1s[j];
        const float* h = h1s + r * 132;
        #pragma unroll 8
        for (int d = 0; d < 128; d++) a += W1t[d * 65 + j] * h[d];
        fes[r * 68 + j] = fmaxf(a, 0.0f);
    }
    __syncthreads();

    // ---- phase 3: e = feat @ W2^T + b2, 8 x 128 = 1024 items ----
    #pragma unroll
    for (int p = 0; p < 4; p++) {
        const int idx = p * 256 + tid;
        const int r = idx >> 7, t = idx & 127;
        float a = b2s[t];
        const float* f = fes + r * 68;
        #pragma unroll 8
        for (int d = 0; d < 64; d++) a += W2t[d * 129 + t] * f[d];
        es[r * 132 + t] = a;
    }
    __syncthreads();

    // ---- phase 4: logits = e @ Wa^T + ba, 8 x 9 = 72 items ----
    if (tid < 72) {
        const int r = tid / 9, j = tid - r * 9;
        float a = bas[j];
        const float* w = Was + j * 129;
        const float* e = es + r * 132;
        #pragma unroll 8
        for (int d = 0; d < 128; d++) a += w[d] * e[d];
        lgs[r * 12 + j] = a;
    }
    __syncthreads();

    // ---- phase 5: softmax + masked renorm, one thread per row ----
    if (tid < 8) {
        const int r = tid, b = b0 + r;
        float lg[9];
        float mx = -1e30f;
        #pragma unroll
        for (int j = 0; j < 9; j++) { lg[j] = lgs[r * 12 + j]; mx = fmaxf(mx, lg[j]); }
        float se = 0.0f;
        #pragma unroll
        for (int j = 0; j < 9; j++) { lg[j] = expf(lg[j] - mx); se += lg[j]; }
        float inv = 1.0f / se;
        float p[9], mk[9], msum = 0.0f;
        #pragma unroll
        for (int j = 0; j < 9; j++) {
            p[j] = lg[j] * inv;
            mk[j] = p[j] * mask[(size_t)b * 9 + j];
            msum += mk[j];
        }
        if (msum > 0.0f) {
            float minv = 1.0f / msum;
            #pragma unroll
            for (int j = 0; j < 9; j++) out[(size_t)b * 9 + j] = mk[j] * minv;
        } else {
            #pragma unroll
            for (int j = 0; j < 9; j++) out[(size_t)b * 9 + j] = p[j];
        }
    }
}

// ============================================================
// launcher
// ============================================================
extern "C" void kernel_launch(void* const* d_in, const int* in_sizes, int n_in,
                              void* d_out, int out_size)
{
    const int*   ability_ids = (const int*)d_in[0];
    const int*   move_ids    = (const int*)d_in[1];
    const float* numerical   = (const float*)d_in[2];
    const float* mask        = (const float*)d_in[3];
    const float* h0          = (const float*)d_in[4];
    const float* c0          = (const float*)d_in[5];
    const float* ability_emb = (const float*)d_in[6];
    const float* move_emb    = (const float*)d_in[7];
    const float* num_W       = (const float*)d_in[8];
    const float* num_b       = (const float*)d_in[9];
    const float* Wih         = (const float*)d_in[10];
    const float* Whh         = (const float*)d_in[11];
    const float* bih         = (const float*)d_in[12];
    const float* bhh         = (const float*)d_in[13];
    const float* W1          = (const float*)d_in[14];
    const float* b1          = (const float*)d_in[15];
    const float* W2          = (const float*)d_in[16];
    const float* b2          = (const float*)d_in[17];
    const float* Wa          = (const float*)d_in[18];
    const float* ba          = (const float*)d_in[19];
    float* out = (float*)d_out;

    cudaFuncSetAttribute(gemm_kernel, cudaFuncAttributeMaxDynamicSharedMemorySize, GEMM_SMEM);
    cudaFuncSetAttribute(pack_extra_kernel, cudaFuncAttributeMaxDynamicSharedMemorySize, EX_SMEM);
    cudaFuncSetAttribute(tail_kernel, cudaFuncAttributeMaxDynamicSharedMemorySize, TAIL_SMEM);

    pack_stream_kernel<<<1112, 256>>>(ability_emb, move_emb, Wih, Whh);
    pack_extra_kernel<<<NB / 32, 256, EX_SMEM>>>(numerical, num_W, num_b, h0);
    gemm_kernel<<<dim3(N_G / TN, NB / TM), 256, GEMM_SMEM>>>(ability_ids, move_ids);
    tail_kernel<<<NB / 8, 256, TAIL_SMEM>>>(c0, bih, bhh, W1, b1, W2, b2, Wa, ba, mask, out);
}

// round 14
// speedup vs baseline: 1.6800x; 1.0157x over previous
#include <cuda_runtime.h>
#include <cuda_bf16.h>
#include <math.h>
#include <stdint.h>

#define NB     4096          // batch rows
#define K_EXT  7936          // 7808 + 128 (h0 folded in)
#define N_G    512           // 4*LSTM_HIDDEN
#define TM     128
#define TN     64
#define BK     32
#define NSTAGE 3
#define NT     (K_EXT/BK)    // 248

// ---- scratch (device globals: allocation-free rule) ----
__device__ __align__(16) __nv_bfloat16 g_eah[300 * 128];   // ability emb hi
__device__ __align__(16) __nv_bfloat16 g_eal[300 * 128];   // ability emb lo
__device__ __align__(16) __nv_bfloat16 g_emh[900 * 128];   // move emb hi
__device__ __align__(16) __nv_bfloat16 g_eml[900 * 128];   // move emb lo
__device__ __align__(16) __nv_bfloat16 g_exh[(size_t)NB * 256];  // [num | h0] hi
__device__ __align__(16) __nv_bfloat16 g_exl[(size_t)NB * 256];  // [num | h0] lo
__device__ __align__(16) __nv_bfloat16 g_wh[(size_t)N_G * K_EXT];  // W hi [N][K]
__device__ __align__(16) __nv_bfloat16 g_wl[(size_t)N_G * K_EXT];  // W lo
__device__ __align__(16) float         g_gates[(size_t)NB * N_G];  // fp32 gates (no bias)

__device__ __forceinline__ void split2(float v, __nv_bfloat16& h, __nv_bfloat16& l) {
    h = __float2bfloat16(v);
    l = __float2bfloat16(v - __bfloat162float(h));
}

// ============================================================
// 1a) pack_stream: embpack + wpack, NO dynamic smem (occupancy uncapped)
// ============================================================
__global__ __launch_bounds__(256)
void pack_stream_kernel(const float* __restrict__ aemb, const float* __restrict__ memb,
                        const float* __restrict__ Wih, const float* __restrict__ Whh)
{
    const int bx = blockIdx.x;
    const int tid = threadIdx.x;

    if (bx < 600) {
        // ---- embpack: 2 rows of the emb tables per block ----
        const int r = bx * 2 + (tid >> 7), t = tid & 127;
        __nv_bfloat16 h, l;
        if (r < 300) {
            split2(aemb[r * 128 + t], h, l);
            g_eah[r * 128 + t] = h;
            g_eal[r * 128 + t] = l;
        } else {
            int rr = r - 300;
            split2(memb[rr * 128 + t], h, l);
            g_emh[rr * 128 + t] = h;
            g_eml[rr * 128 + t] = l;
        }
    } else {
        // ---- wpack: one [Wih|Whh] row -> bf16 hi/lo ----
        const int n = bx - 600;
        for (int i4 = tid; i4 < K_EXT / 4; i4 += 256) {
            int k = i4 * 4;
            float4 v = (k < 7808) ? *(const float4*)(Wih + (size_t)n * 7808 + k)
                                  : *(const float4*)(Whh + n * 128 + (k - 7808));
            __nv_bfloat16 h0_, h1_, h2_, h3_, l0_, l1_, l2_, l3_;
            split2(v.x, h0_, l0_); split2(v.y, h1_, l1_);
            split2(v.z, h2_, l2_); split2(v.w, h3_, l3_);
            __nv_bfloat162 ph01{h0_, h1_}, ph23{h2_, h3_}, pl01{l0_, l1_}, pl23{l2_, l3_};
            uint2 uh, ul;
            uh.x = *(uint32_t*)&ph01; uh.y = *(uint32_t*)&ph23;
            ul.x = *(uint32_t*)&pl01; ul.y = *(uint32_t*)&pl23;
            size_t off = (size_t)n * K_EXT + k;
            *(uint2*)(g_wh + off) = uh;
            *(uint2*)(g_wl + off) = ul;
        }
    }
}

// ============================================================
// 1b) pack_extra: numproj + h0 -> [B][256] bf16 hi/lo (needs 54KB smem)
// ============================================================
#define EX_SMEM ((128 * 85 + 32 * 84) * 4)   // 54272 bytes

__global__ __launch_bounds__(256)
void pack_extra_kernel(const float* __restrict__ numerical, const float* __restrict__ num_W,
                       const float* __restrict__ num_b, const float* __restrict__ h0)
{
    extern __shared__ float exsm[];
    float* Ws  = exsm;               // [128][85]
    float* nrs = exsm + 128 * 85;    // [32][84]
    const int tid = threadIdx.x;
    const int m0 = blockIdx.x * 32;

    for (int i = tid; i < 128 * 84; i += 256) {
        int t = i / 84, d = i - t * 84;
        Ws[t * 85 + d] = num_W[i];
    }
    for (int i = tid; i < 32 * 84; i += 256)
        nrs[i] = numerical[(size_t)m0 * 84 + i];
    __syncthreads();

    const int t = tid & 127, rbase = tid >> 7;
    const float nb = num_b[t];
    const float* w = Ws + t * 85;
    for (int rr = rbase; rr < 32; rr += 2) {
        const float* nr = nrs + rr * 84;
        float acc = nb;
        #pragma unroll 4
        for (int d = 0; d < 84; d++) acc += w[d] * nr[d];
        __nv_bfloat16 h, l;
        split2(acc, h, l);
        g_exh[(size_t)(m0 + rr) * 256 + t] = h;
        g_exl[(size_t)(m0 + rr) * 256 + t] = l;
    }
    for (int i = tid; i < 32 * 128; i += 256) {
        int r = i >> 7, d = i & 127;
        __nv_bfloat16 h, l;
        split2(h0[(size_t)(m0 + r) * 128 + d], h, l);
        g_exh[(size_t)(m0 + r) * 256 + 128 + d] = h;
        g_exl[(size_t)(m0 + r) * 256 + 128 + d] = l;
    }
}

// ============================================================
// 2) GEMM: gates[4096][512] = x @ W^T (3-term bf16 split)
//    R10 config (proven): CTA 128x64, 256 thr, warp 32x32, BK=32,
//    cp.async 3-stage, ldmatrix + mma.sync.m16n8k16.
//    R14: hi LDSMs first, hi-hi MMAs under the lo-LDSM shadow.
// ============================================================
#define LDP 40                          // padded leading dim (elements)
#define A_STAGE_B (TM * LDP * 2)        // 10240 bytes per (hi|lo)
#define B_STAGE_B (TN * LDP * 2)        // 5120 bytes per (hi|lo)
#define OFF_AL    (A_STAGE_B)           // 10240
#define OFF_BH    (2 * A_STAGE_B)       // 20480
#define OFF_BL    (2 * A_STAGE_B + B_STAGE_B)  // 25600
#define STAGE_B   (2 * A_STAGE_B + 2 * B_STAGE_B)  // 30720
#define IDS_B     (128 * 60 * 2)        // 15360 (u16 id table)
#define SM_STG    IDS_B
#define GEMM_SMEM (IDS_B + NSTAGE * STAGE_B)   // 107520

__device__ __forceinline__ uint32_t smem_u32(const void* p) {
    uint32_t a;
    asm("{ .reg .u64 t; cvta.to.shared.u64 t, %1; cvt.u32.u64 %0, t; }" : "=r"(a) : "l"(p));
    return a;
}
__device__ __forceinline__ void cp16(uint32_t s, const void* g) {
    asm volatile("cp.async.cg.shared.global [%0], [%1], 16;" :: "r"(s), "l"(g));
}
#define LDSM4(r, addr) \
    asm volatile("ldmatrix.sync.aligned.m8n8.x4.shared.b16 {%0,%1,%2,%3}, [%4];" \
        : "=r"((r)[0]), "=r"((r)[1]), "=r"((r)[2]), "=r"((r)[3]) : "r"(addr))
#define MMA16816(c, a, b0, b1) \
    asm volatile("mma.sync.aligned.m16n8k16.row.col.f32.bf16.bf16.f32 " \
        "{%0,%1,%2,%3}, {%4,%5,%6,%7}, {%8,%9}, {%0,%1,%2,%3};" \
        : "+f"((c)[0]), "+f"((c)[1]), "+f"((c)[2]), "+f"((c)[3]) \
        : "r"((a)[0]), "r"((a)[1]), "r"((a)[2]), "r"((a)[3]), "r"(b0), "r"(b1))

__global__ __launch_bounds__(256, 2)
void gemm_kernel(const int* __restrict__ aid, const int* __restrict__ mid)
{
    extern __shared__ char smbase[];
    const uint32_t sb = smem_u32(smbase);
    const int tid = threadIdx.x;
    const int n0 = blockIdx.x * TN;
    const int m0 = blockIdx.y * TM;

    // ---- load id table: sid[r][0..11]=ability, sid[r][12..59]=move ----
    uint16_t* sid = (uint16_t*)smbase;
    {
        const int* asrc = aid + (size_t)m0 * 12;     // 1536 contiguous ints
        const int* msrc = mid + (size_t)m0 * 48;     // 6144 contiguous ints
        for (int i = tid; i < 1536; i += 256) {
            int r = i / 12, s = i % 12;
            sid[r * 60 + s] = (uint16_t)asrc[i];
        }
        for (int i = tid; i < 6144; i += 256) {
            int r = i / 48, s = i % 48;
            sid[r * 60 + 12 + s] = (uint16_t)msrc[i];
        }
    }
    __syncthreads();

    // ---- per-thread cp.async roles: A rows r0, r0+64 (hi+lo), B row r0, chunk c ----
    const int r0 = tid >> 2;             // 0..63
    const int r1 = r0 + 64;
    const int c  = tid & 3;              // 16B chunk within 64B k-row
    const uint32_t soff_a0h = r0 * (LDP * 2) + c * 16;
    const uint32_t soff_a1h = r1 * (LDP * 2) + c * 16;
    const uint32_t soff_a0l = OFF_AL + r0 * (LDP * 2) + c * 16;
    const uint32_t soff_a1l = OFF_AL + r1 * (LDP * 2) + c * 16;
    const uint32_t soff_bh  = OFF_BH + r0 * (LDP * 2) + c * 16;
    const uint32_t soff_bl  = OFF_BL + r0 * (LDP * 2) + c * 16;
    const char* bsrc_h = (const char*)(g_wh + (size_t)(n0 + r0) * K_EXT) + c * 16;
    const char* bsrc_l = (const char*)(g_wl + (size_t)(n0 + r0) * K_EXT) + c * 16;

    auto prefetch = [&](int ss, int buf) {
        const uint32_t dst = sb + SM_STG + buf * STAGE_B;
        const int k = ss * BK + c * 8;
        const char *a0h, *a1h, *a0l, *a1l;
        if (k < 7680) {
            const int s = k >> 7, d = k & 127;
            const int id0 = sid[r0 * 60 + s];
            const int id1 = sid[r1 * 60 + s];
            if (s < 12) {
                a0h = (const char*)(g_eah + id0 * 128 + d);
                a0l = (const char*)(g_eal + id0 * 128 + d);
                a1h = (const char*)(g_eah + id1 * 128 + d);
                a1l = (const char*)(g_eal + id1 * 128 + d);
            } else {
                a0h = (const char*)(g_emh + id0 * 128 + d);
                a0l = (const char*)(g_eml + id0 * 128 + d);
                a1h = (const char*)(g_emh + id1 * 128 + d);
                a1l = (const char*)(g_eml + id1 * 128 + d);
            }
        } else {
            const int d = k - 7680;
            a0h = (const char*)(g_exh + (size_t)(m0 + r0) * 256 + d);
            a0l = (const char*)(g_exl + (size_t)(m0 + r0) * 256 + d);
            a1h = (const char*)(g_exh + (size_t)(m0 + r1) * 256 + d);
            a1l = (const char*)(g_exl + (size_t)(m0 + r1) * 256 + d);
        }
        cp16(dst + soff_a0h, a0h);
        cp16(dst + soff_a1h, a1h);
        cp16(dst + soff_a0l, a0l);
        cp16(dst + soff_a1l, a1l);
        cp16(dst + soff_bh, bsrc_h + (size_t)ss * (BK * 2));
        cp16(dst + soff_bl, bsrc_l + (size_t)ss * (BK * 2));
        asm volatile("cp.async.commit_group;" ::: "memory");
    };

    const int wid = tid >> 5;
    const int lane = tid & 31;
    const int wm = wid & 3;              // 4 warps along M (32 rows each)
    const int wn = wid >> 2;             // 2 warps along N (32 cols each)

    // ---- ldmatrix lane-address element offsets (within stage, in elements) ----
    const int arow = lane & 15;
    const int akh  = (lane >> 4) << 3;
    int aoff[2];
    #pragma unroll
    for (int i = 0; i < 2; i++)
        aoff[i] = (wm * 32 + i * 16 + arow) * LDP + akh;
    const int bn  = (lane & 7) + ((lane >> 4) << 3);
    const int bkh = ((lane >> 3) & 1) << 3;
    int boff[2];
    #pragma unroll
    for (int p = 0; p < 2; p++)
        boff[p] = (wn * 32 + p * 16 + bn) * LDP + bkh;

    float acc[2][4][4];   // [m-tile][n8-tile][frag]
    #pragma unroll
    for (int i = 0; i < 2; i++)
        #pragma unroll
        for (int j = 0; j < 4; j++)
            #pragma unroll
            for (int q = 0; q < 4; q++) acc[i][j][q] = 0.0f;

    // ---- prologue: stages 0,1 in flight ----
    prefetch(0, 0);
    prefetch(1, 1);

    #pragma unroll 1
    for (int t = 0; t < NT; ++t) {
        asm volatile("cp.async.wait_group 1;" ::: "memory");
        __syncthreads();   // stage t visible; all warps done with stage t-1

        if (t + 2 < NT) {
            prefetch(t + 2, (t + 2) % NSTAGE);
        } else {
            asm volatile("cp.async.commit_group;" ::: "memory");  // keep group count uniform
        }

        const uint32_t stg_u = sb + SM_STG + (t % NSTAGE) * STAGE_B;
        const uint32_t Ah_u = stg_u;
        const uint32_t Al_u = stg_u + OFF_AL;
        const uint32_t Bh_u = stg_u + OFF_BH;
        const uint32_t Bl_u = stg_u + OFF_BL;

        #pragma unroll
        for (int sub = 0; sub < 2; sub++) {
            const int k16 = sub * 16;
            uint32_t ah[2][4], al[2][4], bh[2][4], bl[2][4];
            // hi LDSMs FIRST (feed hi-hi MMAs earliest)...
            #pragma unroll
            for (int i = 0; i < 2; i++) LDSM4(ah[i], Ah_u + (uint32_t)(aoff[i] + k16) * 2);
            #pragma unroll
            for (int p = 0; p < 2; p++) LDSM4(bh[p], Bh_u + (uint32_t)(boff[p] + k16) * 2);
            // ...then lo LDSMs (their latency hides under the hi-hi MMA block)
            #pragma unroll
            for (int i = 0; i < 2; i++) LDSM4(al[i], Al_u + (uint32_t)(aoff[i] + k16) * 2);
            #pragma unroll
            for (int p = 0; p < 2; p++) LDSM4(bl[p], Bl_u + (uint32_t)(boff[p] + k16) * 2);
            // 8 hi-hi MMAs (only depend on the first 4 LDSMs)
            #pragma unroll
            for (int i = 0; i < 2; i++)
                #pragma unroll
                for (int j = 0; j < 4; j++) {
                    const int p = j >> 1, h = (j & 1) * 2;
                    MMA16816(acc[i][j], ah[i], bh[p][h], bh[p][h + 1]);
                }
            // 16 mixed-term MMAs
            #pragma unroll
            for (int i = 0; i < 2; i++)
                #pragma unroll
                for (int j = 0; j < 4; j++) {
                    const int p = j >> 1, h = (j & 1) * 2;
                    MMA16816(acc[i][j], al[i], bh[p][h], bh[p][h + 1]);
                    MMA16816(acc[i][j], ah[i], bl[p][h], bl[p][h + 1]);
                }
        }
    }

    // ---- epilogue: direct coalesced STG from accumulators (tail adds biases) ----
    asm volatile("cp.async.wait_group 0;" ::: "memory");
    const int erow = lane >> 2;          // 0..7
    const int ecol = (lane & 3) * 2;     // 0,2,4,6
    #pragma unroll
    for (int i = 0; i < 2; i++) {
        #pragma unroll
        for (int j = 0; j < 4; j++) {
            const int gm = m0 + wm * 32 + i * 16 + erow;
            const int gn = n0 + wn * 32 + j * 8 + ecol;
            float2 v0{acc[i][j][0], acc[i][j][1]};
            float2 v1{acc[i][j][2], acc[i][j][3]};
            *(float2*)(g_gates + (size_t)gm * N_G + gn) = v0;
            *(float2*)(g_gates + (size_t)(gm + 8) * N_G + gn) = v1;
        }
    }
}

// ============================================================
// 3) tail: 16 rows per block (weight staging amortized 2x vs R13),
//    ALL rows processed in parallel per phase, 5 barriers total.
// ============================================================
__device__ __forceinline__ float sigm(float x) { return 1.0f / (1.0f + expf(-x)); }

#define OFF_H1 (NB * 9)
#define OFF_C1 (NB * 9 + NB * 128)
#define TROWS  16

// dynamic smem float offsets
#define T_W1T   0                          // [128][65]
#define T_W2T   (T_W1T + 128 * 65)         // [64][129]
#define T_WAS   (T_W2T + 64 * 129)         // [9][129]
#define T_BSUM  (T_WAS + 9 * 129)          // [512]
#define T_B1    (T_BSUM + 512)             // [64]
#define T_B2    (T_B1 + 64)                // [128]
#define T_BA    (T_B2 + 128)               // [12]
#define T_H1S   (T_BA + 12)                // [16][132]
#define T_FE    (T_H1S + TROWS * 132)      // [16][68]
#define T_ES    (T_FE + TROWS * 68)        // [16][132]
#define T_LG    (T_ES + TROWS * 132)       // [16][12]
#define T_TOT   (T_LG + TROWS * 12)
#define TAIL_SMEM (T_TOT * 4)              // ~95.9 KB

__global__ __launch_bounds__(256)
void tail_kernel(const float* __restrict__ c0,
                 const float* __restrict__ bih, const float* __restrict__ bhh,
                 const float* __restrict__ W1, const float* __restrict__ b1,
                 const float* __restrict__ W2, const float* __restrict__ b2,
                 const float* __restrict__ Wa, const float* __restrict__ ba,
                 const float* __restrict__ mask, float* __restrict__ out)
{
    extern __shared__ float sm[];
    float* W1t  = sm + T_W1T;    // [d][j] stride 65
    float* W2t  = sm + T_W2T;    // [d][t] stride 129
    float* Was  = sm + T_WAS;    // [j][d] stride 129
    float* bsum = sm + T_BSUM;
    float* b1s  = sm + T_B1;
    float* b2s  = sm + T_B2;
    float* bas  = sm + T_BA;
    float* h1s  = sm + T_H1S;    // [r][t] stride 132
    float* fes  = sm + T_FE;     // [r][j] stride 68
    float* es   = sm + T_ES;     // [r][t] stride 132
    float* lgs  = sm + T_LG;     // [r][j] stride 12

    const int tid = threadIdx.x;
    const int b0 = blockIdx.x * TROWS;

    // ---- stage weights/biases (all coalesced reads) ----
    for (int i = tid; i < 64 * 128; i += 256) {   // W1 [64][128]
        int j = i >> 7, d = i & 127;
        W1t[d * 65 + j] = W1[i];
    }
    for (int i = tid; i < 128 * 64; i += 256) {   // W2 [128][64]
        int t = i >> 6, d = i & 63;
        W2t[d * 129 + t] = W2[i];
    }
    for (int i = tid; i < 9 * 128; i += 256) {    // Wa [9][128]
        int j = i >> 7, d = i & 127;
        Was[j * 129 + d] = Wa[i];
    }
    for (int i = tid; i < 512; i += 256) bsum[i] = bih[i] + bhh[i];
    if (tid < 64) b1s[tid] = b1[tid];
    if (tid < 128) b2s[tid] = b2[tid];
    if (tid < 9) bas[tid] = ba[tid];
    __syncthreads();

    // ---- phase 1: LSTM elementwise, 16 rows x 128 = 2048 items ----
    #pragma unroll
    for (int p = 0; p < 8; p++) {
        const int idx = p * 256 + tid;
        const int r = idx >> 7, t = idx & 127;
        const int b = b0 + r;
        const float* g = g_gates + (size_t)b * N_G;
        float ii = sigm(g[t] + bsum[t]);
        float ff = sigm(g[128 + t] + bsum[128 + t]);
        float gv = tanhf(g[256 + t] + bsum[256 + t]);
        float oo = sigm(g[384 + t] + bsum[384 + t]);
        float c1 = ff * c0[(size_t)b * 128 + t] + ii * gv;
        float h1 = oo * tanhf(c1);
        out[OFF_H1 + (size_t)b * 128 + t] = h1;
        out[OFF_C1 + (size_t)b * 128 + t] = c1;
        h1s[r * 132 + t] = h1;
    }
    __syncthreads();

    // ---- phase 2: feat = relu(h1 @ W1^T + b1), 16 x 64 = 1024 items ----
    #pragma unroll
    for (int p = 0; p < 4; p++) {
        const int idx = p * 256 + tid;
        const int r = idx >> 6, j = idx & 63;
        float a = b1s[j];
        const float* h = h1s + r * 132;
        #pragma unroll 8
        for (int d = 0; d < 128; d++) a += W1t[d * 65 + j] * h[d];
        fes[r * 68 + j] = fmaxf(a, 0.0f);
    }
    __syncthreads();

    // ---- phase 3: e = feat @ W2^T + b2, 16 x 128 = 2048 items ----
    #pragma unroll
    for (int p = 0; p < 8; p++) {
        const int idx = p * 256 + tid;
        const int r = idx >> 7, t = idx & 127;
        float a = b2s[t];
        const float* f = fes + r * 68;
        #pragma unroll 8
        for (int d = 0; d < 64; d++) a += W2t[d * 129 + t] * f[d];
        es[r * 132 + t] = a;
    }
    __syncthreads();

    // ---- phase 4: logits = e @ Wa^T + ba, 16 x 9 = 144 items ----
    if (tid < 144) {
        const int r = tid / 9, j = tid - r * 9;
        float a = bas[j];
        const float* w = Was + j * 129;
        const float* e = es + r * 132;
        #pragma unroll 8
        for (int d = 0; d < 128; d++) a += w[d] * e[d];
        lgs[r * 12 + j] = a;
    }
    __syncthreads();

    // ---- phase 5: softmax + masked renorm, one thread per row ----
    if (tid < TROWS) {
        const int r = tid, b = b0 + r;
        float lg[9];
        float mx = -1e30f;
        #pragma unroll
        for (int j = 0; j < 9; j++) { lg[j] = lgs[r * 12 + j]; mx = fmaxf(mx, lg[j]); }
        float se = 0.0f;
        #pragma unroll
        for (int j = 0; j < 9; j++) { lg[j] = expf(lg[j] - mx); se += lg[j]; }
        float inv = 1.0f / se;
        float p[9], mk[9], msum = 0.0f;
        #pragma unroll
        for (int j = 0; j < 9; j++) {
            p[j] = lg[j] * inv;
            mk[j] = p[j] * mask[(size_t)b * 9 + j];
            msum += mk[j];
        }
        if (msum > 0.0f) {
            float minv = 1.0f / msum;
            #pragma unroll
            for (int j = 0; j < 9; j++) out[(size_t)b * 9 + j] = mk[j] * minv;
        } else {
            #pragma unroll
            for (int j = 0; j < 9; j++) out[(size_t)b * 9 + j] = p[j];
        }
    }
}

// ============================================================
// launcher
// ============================================================
extern "C" void kernel_launch(void* const* d_in, const int* in_sizes, int n_in,
                              void* d_out, int out_size)
{
    const int*   ability_ids = (const int*)d_in[0];
    const int*   move_ids    = (const int*)d_in[1];
    const float* numerical   = (const float*)d_in[2];
    const float* mask        = (const float*)d_in[3];
    const float* h0          = (const float*)d_in[4];
    const float* c0          = (const float*)d_in[5];
    const float* ability_emb = (const float*)d_in[6];
    const float* move_emb    = (const float*)d_in[7];
    const float* num_W       = (const float*)d_in[8];
    const float* num_b       = (const float*)d_in[9];
    const float* Wih         = (const float*)d_in[10];
    const float* Whh         = (const float*)d_in[11];
    const float* bih         = (const float*)d_in[12];
    const float* bhh         = (const float*)d_in[13];
    const float* W1          = (const float*)d_in[14];
    const float* b1          = (const float*)d_in[15];
    const float* W2          = (const float*)d_in[16];
    const float* b2          = (const float*)d_in[17];
    const float* Wa          = (const float*)d_in[18];
    const float* ba          = (const float*)d_in[19];
    float* out = (float*)d_out;

    cudaFuncSetAttribute(gemm_kernel, cudaFuncAttributeMaxDynamicSharedMemorySize, GEMM_SMEM);
    cudaFuncSetAttribute(pack_extra_kernel, cudaFuncAttributeMaxDynamicSharedMemorySize, EX_SMEM);
    cudaFuncSetAttribute(tail_kernel, cudaFuncAttributeMaxDynamicSharedMemorySize, TAIL_SMEM);

    pack_stream_kernel<<<1112, 256>>>(ability_emb, move_emb, Wih, Whh);
    pack_extra_kernel<<<NB / 32, 256, EX_SMEM>>>(numerical, num_W, num_b, h0);
    gemm_kernel<<<dim3(N_G / TN, NB / TM), 256, GEMM_SMEM>>>(ability_ids, move_ids);
    tail_kernel<<<NB / TROWS, 256, TAIL_SMEM>>>(c0, bih, bhh, W1, b1, W2, b2, Wa, ba, mask, out);
}

// round 15
// speedup vs baseline: 2.2116x; 1.3164x over previous
#include <cuda_runtime.h>
#include <cuda_fp16.h>
#include <math.h>
#include <stdint.h>

#define NB     4096          // batch rows
#define K_EXT  7936          // 7808 + 128 (h0 folded in)
#define N_G    512           // 4*LSTM_HIDDEN
#define TM     128
#define TN     64
#define BK     32
#define NSTAGE 3
#define NT     (K_EXT/BK)    // 248

// ---- scratch (device globals: allocation-free rule) ----
__device__ __align__(16) __half g_eah[300 * 128];   // ability emb hi (fp16)
__device__ __align__(16) __half g_eal[300 * 128];   // ability emb lo
__device__ __align__(16) __half g_emh[900 * 128];   // move emb hi
__device__ __align__(16) __half g_eml[900 * 128];   // move emb lo
__device__ __align__(16) __half g_exh[(size_t)NB * 256];  // [num | h0] hi
__device__ __align__(16) __half g_exl[(size_t)NB * 256];  // [num | h0] lo
__device__ __align__(16) __half g_w[(size_t)N_G * K_EXT]; // W single fp16 [N][K]
__device__ __align__(16) float  g_gates[(size_t)NB * N_G];  // fp32 gates (no bias)

__device__ __forceinline__ void split2h(float v, __half& h, __half& l) {
    h = __float2half(v);
    l = __float2half(v - __half2float(h));
}

// ============================================================
// 1a) pack_stream: embpack + wpack, NO dynamic smem (occupancy uncapped)
// ============================================================
__global__ __launch_bounds__(256)
void pack_stream_kernel(const float* __restrict__ aemb, const float* __restrict__ memb,
                        const float* __restrict__ Wih, const float* __restrict__ Whh)
{
    const int bx = blockIdx.x;
    const int tid = threadIdx.x;

    if (bx < 600) {
        // ---- embpack: 2 rows of the emb tables per block (fp16 hi/lo) ----
        const int r = bx * 2 + (tid >> 7), t = tid & 127;
        __half h, l;
        if (r < 300) {
            split2h(aemb[r * 128 + t], h, l);
            g_eah[r * 128 + t] = h;
            g_eal[r * 128 + t] = l;
        } else {
            int rr = r - 300;
            split2h(memb[rr * 128 + t], h, l);
            g_emh[rr * 128 + t] = h;
            g_eml[rr * 128 + t] = l;
        }
    } else {
        // ---- wpack: one [Wih|Whh] row -> single fp16 ----
        const int n = bx - 600;
        for (int i4 = tid; i4 < K_EXT / 4; i4 += 256) {
            int k = i4 * 4;
            float4 v = (k < 7808) ? *(const float4*)(Wih + (size_t)n * 7808 + k)
                                  : *(const float4*)(Whh + n * 128 + (k - 7808));
            __half2 p01{__float2half(v.x), __float2half(v.y)};
            __half2 p23{__float2half(v.z), __float2half(v.w)};
            uint2 u;
            u.x = *(uint32_t*)&p01; u.y = *(uint32_t*)&p23;
            *(uint2*)(g_w + (size_t)n * K_EXT + k) = u;
        }
    }
}

// ============================================================
// 1b) pack_extra: numproj + h0 -> [B][256] fp16 hi/lo (needs 54KB smem)
// ============================================================
#define EX_SMEM ((128 * 85 + 32 * 84) * 4)   // 54272 bytes

__global__ __launch_bounds__(256)
void pack_extra_kernel(const float* __restrict__ numerical, const float* __restrict__ num_W,
                       const float* __restrict__ num_b, const float* __restrict__ h0)
{
    extern __shared__ float exsm[];
    float* Ws  = exsm;               // [128][85]
    float* nrs = exsm + 128 * 85;    // [32][84]
    const int tid = threadIdx.x;
    const int m0 = blockIdx.x * 32;

    for (int i = tid; i < 128 * 84; i += 256) {
        int t = i / 84, d = i - t * 84;
        Ws[t * 85 + d] = num_W[i];
    }
    for (int i = tid; i < 32 * 84; i += 256)
        nrs[i] = numerical[(size_t)m0 * 84 + i];
    __syncthreads();

    const int t = tid & 127, rbase = tid >> 7;
    const float nb = num_b[t];
    const float* w = Ws + t * 85;
    for (int rr = rbase; rr < 32; rr += 2) {
        const float* nr = nrs + rr * 84;
        float acc = nb;
        #pragma unroll 4
        for (int d = 0; d < 84; d++) acc += w[d] * nr[d];
        __half h, l;
        split2h(acc, h, l);
        g_exh[(size_t)(m0 + rr) * 256 + t] = h;
        g_exl[(size_t)(m0 + rr) * 256 + t] = l;
    }
    for (int i = tid; i < 32 * 128; i += 256) {
        int r = i >> 7, d = i & 127;
        __half h, l;
        split2h(h0[(size_t)(m0 + r) * 128 + d], h, l);
        g_exh[(size_t)(m0 + r) * 256 + 128 + d] = h;
        g_exl[(size_t)(m0 + r) * 256 + 128 + d] = l;
    }
}

// ============================================================
// 2) GEMM: gates[4096][512] = x @ W^T (fp16 2-term: xh*W + xl*W)
//    CTA 128x64, 256 thr, warp 32x32, BK=32, cp.async 3-stage,
//    ldmatrix + mma.sync.m16n8k16.f16. A gathered on-the-fly.
// ============================================================
#define LDP 40                          // padded leading dim (elements)
#define A_STAGE_B (TM * LDP * 2)        // 10240 bytes per (hi|lo)
#define B_STAGE_B (TN * LDP * 2)        // 5120 bytes (single)
#define OFF_AL    (A_STAGE_B)           // 10240
#define OFF_B     (2 * A_STAGE_B)       // 20480
#define STAGE_B   (2 * A_STAGE_B + B_STAGE_B)  // 25600
#define IDS_B     (128 * 60 * 2)        // 15360 (u16 id table)
#define SM_STG    IDS_B
#define GEMM_SMEM (IDS_B + NSTAGE * STAGE_B)   // 92160

__device__ __forceinline__ uint32_t smem_u32(const void* p) {
    uint32_t a;
    asm("{ .reg .u64 t; cvta.to.shared.u64 t, %1; cvt.u32.u64 %0, t; }" : "=r"(a) : "l"(p));
    return a;
}
__device__ __forceinline__ void cp16(uint32_t s, const void* g) {
    asm volatile("cp.async.cg.shared.global [%0], [%1], 16;" :: "r"(s), "l"(g));
}
#define LDSM4(r, addr) \
    asm volatile("ldmatrix.sync.aligned.m8n8.x4.shared.b16 {%0,%1,%2,%3}, [%4];" \
        : "=r"((r)[0]), "=r"((r)[1]), "=r"((r)[2]), "=r"((r)[3]) : "r"(addr))
#define MMAF16(c, a, b0, b1) \
    asm volatile("mma.sync.aligned.m16n8k16.row.col.f32.f16.f16.f32 " \
        "{%0,%1,%2,%3}, {%4,%5,%6,%7}, {%8,%9}, {%0,%1,%2,%3};" \
        : "+f"((c)[0]), "+f"((c)[1]), "+f"((c)[2]), "+f"((c)[3]) \
        : "r"((a)[0]), "r"((a)[1]), "r"((a)[2]), "r"((a)[3]), "r"(b0), "r"(b1))

__global__ __launch_bounds__(256, 2)
void gemm_kernel(const int* __restrict__ aid, const int* __restrict__ mid)
{
    extern __shared__ char smbase[];
    const uint32_t sb = smem_u32(smbase);
    const int tid = threadIdx.x;
    const int n0 = blockIdx.x * TN;
    const int m0 = blockIdx.y * TM;

    // ---- load id table: sid[r][0..11]=ability, sid[r][12..59]=move ----
    uint16_t* sid = (uint16_t*)smbase;
    {
        const int* asrc = aid + (size_t)m0 * 12;     // 1536 contiguous ints
        const int* msrc = mid + (size_t)m0 * 48;     // 6144 contiguous ints
        for (int i = tid; i < 1536; i += 256) {
            int r = i / 12, s = i % 12;
            sid[r * 60 + s] = (uint16_t)asrc[i];
        }
        for (int i = tid; i < 6144; i += 256) {
            int r = i / 48, s = i % 48;
            sid[r * 60 + 12 + s] = (uint16_t)msrc[i];
        }
    }
    __syncthreads();

    // ---- per-thread cp.async roles: A rows r0, r0+64 (hi+lo), B row r0, chunk c ----
    const int r0 = tid >> 2;             // 0..63
    const int r1 = r0 + 64;
    const int c  = tid & 3;              // 16B chunk within 64B k-row
    const uint32_t soff_a0h = r0 * (LDP * 2) + c * 16;
    const uint32_t soff_a1h = r1 * (LDP * 2) + c * 16;
    const uint32_t soff_a0l = OFF_AL + r0 * (LDP * 2) + c * 16;
    const uint32_t soff_a1l = OFF_AL + r1 * (LDP * 2) + c * 16;
    const uint32_t soff_b   = OFF_B + r0 * (LDP * 2) + c * 16;
    const char* bsrc = (const char*)(g_w + (size_t)(n0 + r0) * K_EXT) + c * 16;

    auto prefetch = [&](int ss, int buf) {
        const uint32_t dst = sb + SM_STG + buf * STAGE_B;
        const int k = ss * BK + c * 8;
        const char *a0h, *a1h, *a0l, *a1l;
        if (k < 7680) {
            const int s = k >> 7, d = k & 127;
            const int id0 = sid[r0 * 60 + s];
            const int id1 = sid[r1 * 60 + s];
            if (s < 12) {
                a0h = (const char*)(g_eah + id0 * 128 + d);
                a0l = (const char*)(g_eal + id0 * 128 + d);
                a1h = (const char*)(g_eah + id1 * 128 + d);
                a1l = (const char*)(g_eal + id1 * 128 + d);
            } else {
                a0h = (const char*)(g_emh + id0 * 128 + d);
                a0l = (const char*)(g_eml + id0 * 128 + d);
                a1h = (const char*)(g_emh + id1 * 128 + d);
                a1l = (const char*)(g_eml + id1 * 128 + d);
            }
        } else {
            const int d = k - 7680;
            a0h = (const char*)(g_exh + (size_t)(m0 + r0) * 256 + d);
            a0l = (const char*)(g_exl + (size_t)(m0 + r0) * 256 + d);
            a1h = (const char*)(g_exh + (size_t)(m0 + r1) * 256 + d);
            a1l = (const char*)(g_exl + (size_t)(m0 + r1) * 256 + d);
        }
        cp16(dst + soff_a0h, a0h);
        cp16(dst + soff_a1h, a1h);
        cp16(dst + soff_a0l, a0l);
        cp16(dst + soff_a1l, a1l);
        cp16(dst + soff_b, bsrc + (size_t)ss * (BK * 2));
        asm volatile("cp.async.commit_group;" ::: "memory");
    };

    const int wid = tid >> 5;
    const int lane = tid & 31;
    const int wm = wid & 3;              // 4 warps along M (32 rows each)
    const int wn = wid >> 2;             // 2 warps along N (32 cols each)

    // ---- ldmatrix lane-address element offsets (within stage, in elements) ----
    const int arow = lane & 15;
    const int akh  = (lane >> 4) << 3;
    int aoff[2];
    #pragma unroll
    for (int i = 0; i < 2; i++)
        aoff[i] = (wm * 32 + i * 16 + arow) * LDP + akh;
    const int bn  = (lane & 7) + ((lane >> 4) << 3);
    const int bkh = ((lane >> 3) & 1) << 3;
    int boff[2];
    #pragma unroll
    for (int p = 0; p < 2; p++)
        boff[p] = (wn * 32 + p * 16 + bn) * LDP + bkh;

    float acc[2][4][4];   // [m-tile][n8-tile][frag]
    #pragma unroll
    for (int i = 0; i < 2; i++)
        #pragma unroll
        for (int j = 0; j < 4; j++)
            #pragma unroll
            for (int q = 0; q < 4; q++) acc[i][j][q] = 0.0f;

    // ---- prologue: stages 0,1 in flight ----
    prefetch(0, 0);
    prefetch(1, 1);

    #pragma unroll 1
    for (int t = 0; t < NT; ++t) {
        asm volatile("cp.async.wait_group 1;" ::: "memory");
        __syncthreads();   // stage t visible; all warps done with stage t-1

        if (t + 2 < NT) {
            prefetch(t + 2, (t + 2) % NSTAGE);
        } else {
            asm volatile("cp.async.commit_group;" ::: "memory");  // keep group count uniform
        }

        const uint32_t stg_u = sb + SM_STG + (t % NSTAGE) * STAGE_B;
        const uint32_t Ah_u = stg_u;
        const uint32_t Al_u = stg_u + OFF_AL;
        const uint32_t B_u  = stg_u + OFF_B;

        #pragma unroll
        for (int sub = 0; sub < 2; sub++) {
            const int k16 = sub * 16;
            uint32_t ah[2][4], al[2][4], bb[2][4];
            // hi + B LDSMs first (feed hi MMAs earliest)...
            #pragma unroll
            for (int i = 0; i < 2; i++) LDSM4(ah[i], Ah_u + (uint32_t)(aoff[i] + k16) * 2);
            #pragma unroll
            for (int p = 0; p < 2; p++) LDSM4(bb[p], B_u + (uint32_t)(boff[p] + k16) * 2);
            // ...then lo LDSMs (latency hides under the hi MMA block)
            #pragma unroll
            for (int i = 0; i < 2; i++) LDSM4(al[i], Al_u + (uint32_t)(aoff[i] + k16) * 2);
            // 8 hi MMAs
            #pragma unroll
            for (int i = 0; i < 2; i++)
                #pragma unroll
                for (int j = 0; j < 4; j++) {
                    const int p = j >> 1, h = (j & 1) * 2;
                    MMAF16(acc[i][j], ah[i], bb[p][h], bb[p][h + 1]);
                }
            // 8 lo MMAs
            #pragma unroll
            for (int i = 0; i < 2; i++)
                #pragma unroll
                for (int j = 0; j < 4; j++) {
                    const int p = j >> 1, h = (j & 1) * 2;
                    MMAF16(acc[i][j], al[i], bb[p][h], bb[p][h + 1]);
                }
        }
    }

    // ---- epilogue: direct coalesced STG from accumulators (tail adds biases) ----
    asm volatile("cp.async.wait_group 0;" ::: "memory");
    const int erow = lane >> 2;          // 0..7
    const int ecol = (lane & 3) * 2;     // 0,2,4,6
    #pragma unroll
    for (int i = 0; i < 2; i++) {
        #pragma unroll
        for (int j = 0; j < 4; j++) {
            const int gm = m0 + wm * 32 + i * 16 + erow;
            const int gn = n0 + wn * 32 + j * 8 + ecol;
            float2 v0{acc[i][j][0], acc[i][j][1]};
            float2 v1{acc[i][j][2], acc[i][j][3]};
            *(float2*)(g_gates + (size_t)gm * N_G + gn) = v0;
            *(float2*)(g_gates + (size_t)(gm + 8) * N_G + gn) = v1;
        }
    }
}

// ============================================================
// 3) tail: 16 rows per block, ALL rows processed in parallel per phase,
//    5 barriers total (R14 proven config).
// ============================================================
__device__ __forceinline__ float sigm(float x) { return 1.0f / (1.0f + expf(-x)); }

#define OFF_H1 (NB * 9)
#define OFF_C1 (NB * 9 + NB * 128)
#define TROWS  16

// dynamic smem float offsets
#define T_W1T   0                          // [128][65]
#define T_W2T   (T_W1T + 128 * 65)         // [64][129]
#define T_WAS   (T_W2T + 64 * 129)         // [9][129]
#define T_BSUM  (T_WAS + 9 * 129)          // [512]
#define T_B1    (T_BSUM + 512)             // [64]
#define T_B2    (T_B1 + 64)                // [128]
#define T_BA    (T_B2 + 128)               // [12]
#define T_H1S   (T_BA + 12)                // [16][132]
#define T_FE    (T_H1S + TROWS * 132)      // [16][68]
#define T_ES    (T_FE + TROWS * 68)        // [16][132]
#define T_LG    (T_ES + TROWS * 132)       // [16][12]
#define T_TOT   (T_LG + TROWS * 12)
#define TAIL_SMEM (T_TOT * 4)              // ~95.9 KB

__global__ __launch_bounds__(256)
void tail_kernel(const float* __restrict__ c0,
                 const float* __restrict__ bih, const float* __restrict__ bhh,
                 const float* __restrict__ W1, const float* __restrict__ b1,
                 const float* __restrict__ W2, const float* __restrict__ b2,
                 const float* __restrict__ Wa, const float* __restrict__ ba,
                 const float* __restrict__ mask, float* __restrict__ out)
{
    extern __shared__ float sm[];
    float* W1t  = sm + T_W1T;    // [d][j] stride 65
    float* W2t  = sm + T_W2T;    // [d][t] stride 129
    float* Was  = sm + T_WAS;    // [j][d] stride 129
    float* bsum = sm + T_BSUM;
    float* b1s  = sm + T_B1;
    float* b2s  = sm + T_B2;
    float* bas  = sm + T_BA;
    float* h1s  = sm + T_H1S;    // [r][t] stride 132
    float* fes  = sm + T_FE;     // [r][j] stride 68
    float* es   = sm + T_ES;     // [r][t] stride 132
    float* lgs  = sm + T_LG;     // [r][j] stride 12

    const int tid = threadIdx.x;
    const int b0 = blockIdx.x * TROWS;

    // ---- stage weights/biases (all coalesced reads) ----
    for (int i = tid; i < 64 * 128; i += 256) {   // W1 [64][128]
        int j = i >> 7, d = i & 127;
        W1t[d * 65 + j] = W1[i];
    }
    for (int i = tid; i < 128 * 64; i += 256) {   // W2 [128][64]
        int t = i >> 6, d = i & 63;
        W2t[d * 129 + t] = W2[i];
    }
    for (int i = tid; i < 9 * 128; i += 256) {    // Wa [9][128]
        int j = i >> 7, d = i & 127;
        Was[j * 129 + d] = Wa[i];
    }
    for (int i = tid; i < 512; i += 256) bsum[i] = bih[i] + bhh[i];
    if (tid < 64) b1s[tid] = b1[tid];
    if (tid < 128) b2s[tid] = b2[tid];
    if (tid < 9) bas[tid] = ba[tid];
    __syncthreads();

    // ---- phase 1: LSTM elementwise, 16 rows x 128 = 2048 items ----
    #pragma unroll
    for (int p = 0; p < 8; p++) {
        const int idx = p * 256 + tid;
        const int r = idx >> 7, t = idx & 127;
        const int b = b0 + r;
        const float* g = g_gates + (size_t)b * N_G;
        float ii = sigm(g[t] + bsum[t]);
        float ff = sigm(g[128 + t] + bsum[128 + t]);
        float gv = tanhf(g[256 + t] + bsum[256 + t]);
        float oo = sigm(g[384 + t] + bsum[384 + t]);
        float c1 = ff * c0[(size_t)b * 128 + t] + ii * gv;
        float h1 = oo * tanhf(c1);
        out[OFF_H1 + (size_t)b * 128 + t] = h1;
        out[OFF_C1 + (size_t)b * 128 + t] = c1;
        h1s[r * 132 + t] = h1;
    }
    __syncthreads();

    // ---- phase 2: feat = relu(h1 @ W1^T + b1), 16 x 64 = 1024 items ----
    #pragma unroll
    for (int p = 0; p < 4; p++) {
        const int idx = p * 256 + tid;
        const int r = idx >> 6, j = idx & 63;
        float a = b1s[j];
        const float* h = h1s + r * 132;
        #pragma unroll 8
        for (int d = 0; d < 128; d++) a += W1t[d * 65 + j] * h[d];
        fes[r * 68 + j] = fmaxf(a, 0.0f);
    }
    __syncthreads();

    // ---- phase 3: e = feat @ W2^T + b2, 16 x 128 = 2048 items ----
    #pragma unroll
    for (int p = 0; p < 8; p++) {
        const int idx = p * 256 + tid;
        const int r = idx >> 7, t = idx & 127;
        float a = b2s[t];
        const float* f = fes + r * 68;
        #pragma unroll 8
        for (int d = 0; d < 64; d++) a += W2t[d * 129 + t] * f[d];
        es[r * 132 + t] = a;
    }
    __syncthreads();

    // ---- phase 4: logits = e @ Wa^T + ba, 16 x 9 = 144 items ----
    if (tid < 144) {
        const int r = tid / 9, j = tid - r * 9;
        float a = bas[j];
        const float* w = Was + j * 129;
        const float* e = es + r * 132;
        #pragma unroll 8
        for (int d = 0; d < 128; d++) a += w[d] * e[d];
        lgs[r * 12 + j] = a;
    }
    __syncthreads();

    // ---- phase 5: softmax + masked renorm, one thread per row ----
    if (tid < TROWS) {
        const int r = tid, b = b0 + r;
        float lg[9];
        float mx = -1e30f;
        #pragma unroll
        for (int j = 0; j < 9; j++) { lg[j] = lgs[r * 12 + j]; mx = fmaxf(mx, lg[j]); }
        float se = 0.0f;
        #pragma unroll
        for (int j = 0; j < 9; j++) { lg[j] = expf(lg[j] - mx); se += lg[j]; }
        float inv = 1.0f / se;
        float p[9], mk[9], msum = 0.0f;
        #pragma unroll
        for (int j = 0; j < 9; j++) {
            p[j] = lg[j] * inv;
            mk[j] = p[j] * mask[(size_t)b * 9 + j];
            msum += mk[j];
        }
        if (msum > 0.0f) {
            float minv = 1.0f / msum;
            #pragma unroll
            for (int j = 0; j < 9; j++) out[(size_t)b * 9 + j] = mk[j] * minv;
        } else {
            #pragma unroll
            for (int j = 0; j < 9; j++) out[(size_t)b * 9 + j] = p[j];
        }
    }
}

// ============================================================
// launcher
// ============================================================
extern "C" void kernel_launch(void* const* d_in, const int* in_sizes, int n_in,
                              void* d_out, int out_size)
{
    const int*   ability_ids = (const int*)d_in[0];
    const int*   move_ids    = (const int*)d_in[1];
    const float* numerical   = (const float*)d_in[2];
    const float* mask        = (const float*)d_in[3];
    const float* h0          = (const float*)d_in[4];
    const float* c0          = (const float*)d_in[5];
    const float* ability_emb = (const float*)d_in[6];
    const float* move_emb    = (const float*)d_in[7];
    const float* num_W       = (const float*)d_in[8];
    const float* num_b       = (const float*)d_in[9];
    const float* Wih         = (const float*)d_in[10];
    const float* Whh         = (const float*)d_in[11];
    const float* bih         = (const float*)d_in[12];
    const float* bhh         = (const float*)d_in[13];
    const float* W1          = (const float*)d_in[14];
    const float* b1          = (const float*)d_in[15];
    const float* W2          = (const float*)d_in[16];
    const float* b2          = (const float*)d_in[17];
    const float* Wa          = (const float*)d_in[18];
    const float* ba          = (const float*)d_in[19];
    float* out = (float*)d_out;

    cudaFuncSetAttribute(gemm_kernel, cudaFuncAttributeMaxDynamicSharedMemorySize, GEMM_SMEM);
    cudaFuncSetAttribute(pack_extra_kernel, cudaFuncAttributeMaxDynamicSharedMemorySize, EX_SMEM);
    cudaFuncSetAttribute(tail_kernel, cudaFuncAttributeMaxDynamicSharedMemorySize, TAIL_SMEM);

    pack_stream_kernel<<<1112, 256>>>(ability_emb, move_emb, Wih, Whh);
    pack_extra_kernel<<<NB / 32, 256, EX_SMEM>>>(numerical, num_W, num_b, h0);
    gemm_kernel<<<dim3(N_G / TN, NB / TM), 256, GEMM_SMEM>>>(ability_ids, move_ids);
    tail_kernel<<<NB / TROWS, 256, TAIL_SMEM>>>(c0, bih, bhh, W1, b1, W2, b2, Wa, ba, mask, out);
}

// round 16
// speedup vs baseline: 3.4254x; 1.5489x over previous
#include <cuda_runtime.h>
#include <cuda_fp16.h>
#include <math.h>
#include <stdint.h>

#define NB     4096          // batch rows
#define K_EXT  7936          // 7808 + 128 (h0 folded in)
#define N_G    512           // 4*LSTM_HIDDEN
#define TM     128
#define TN     64
#define BK     32
#define NSTAGE 3
#define NT     (K_EXT/BK)    // 248

// ---- scratch (device globals: allocation-free rule) ----
__device__ __align__(16) __half g_ea[300 * 128];    // ability emb (fp16)
__device__ __align__(16) __half g_em[900 * 128];    // move emb
__device__ __align__(16) __half g_ex[(size_t)NB * 256];   // [num | h0]
__device__ __align__(16) __half g_w[(size_t)N_G * K_EXT]; // W fp16 [N][K]
__device__ __align__(16) float  g_gates[(size_t)NB * N_G];  // fp32 gates (no bias)

// ============================================================
// 1a) pack_stream: embpack + wpack, NO dynamic smem (occupancy uncapped)
// ============================================================
__global__ __launch_bounds__(256)
void pack_stream_kernel(const float* __restrict__ aemb, const float* __restrict__ memb,
                        const float* __restrict__ Wih, const float* __restrict__ Whh)
{
    const int bx = blockIdx.x;
    const int tid = threadIdx.x;

    if (bx < 600) {
        // ---- embpack: 2 rows of the emb tables per block (single fp16) ----
        const int r = bx * 2 + (tid >> 7), t = tid & 127;
        if (r < 300) {
            g_ea[r * 128 + t] = __float2half(aemb[r * 128 + t]);
        } else {
            int rr = r - 300;
            g_em[rr * 128 + t] = __float2half(memb[rr * 128 + t]);
        }
    } else {
        // ---- wpack: one [Wih|Whh] row -> single fp16 ----
        const int n = bx - 600;
        for (int i4 = tid; i4 < K_EXT / 4; i4 += 256) {
            int k = i4 * 4;
            float4 v = (k < 7808) ? *(const float4*)(Wih + (size_t)n * 7808 + k)
                                  : *(const float4*)(Whh + n * 128 + (k - 7808));
            __half2 p01{__float2half(v.x), __float2half(v.y)};
            __half2 p23{__float2half(v.z), __float2half(v.w)};
            uint2 u;
            u.x = *(uint32_t*)&p01; u.y = *(uint32_t*)&p23;
            *(uint2*)(g_w + (size_t)n * K_EXT + k) = u;
        }
    }
}

// ============================================================
// 1b) pack_extra: numproj + h0 -> [B][256] single fp16 (needs 54KB smem)
// ============================================================
#define EX_SMEM ((128 * 85 + 32 * 84) * 4)   // 54272 bytes

__global__ __launch_bounds__(256)
void pack_extra_kernel(const float* __restrict__ numerical, const float* __restrict__ num_W,
                       const float* __restrict__ num_b, const float* __restrict__ h0)
{
    extern __shared__ float exsm[];
    float* Ws  = exsm;               // [128][85]
    float* nrs = exsm + 128 * 85;    // [32][84]
    const int tid = threadIdx.x;
    const int m0 = blockIdx.x * 32;

    for (int i = tid; i < 128 * 84; i += 256) {
        int t = i / 84, d = i - t * 84;
        Ws[t * 85 + d] = num_W[i];
    }
    for (int i = tid; i < 32 * 84; i += 256)
        nrs[i] = numerical[(size_t)m0 * 84 + i];
    __syncthreads();

    const int t = tid & 127, rbase = tid >> 7;
    const float nb = num_b[t];
    const float* w = Ws + t * 85;
    for (int rr = rbase; rr < 32; rr += 2) {
        const float* nr = nrs + rr * 84;
        float acc = nb;
        #pragma unroll 4
        for (int d = 0; d < 84; d++) acc += w[d] * nr[d];
        g_ex[(size_t)(m0 + rr) * 256 + t] = __float2half(acc);
    }
    for (int i = tid; i < 32 * 128; i += 256) {
        int r = i >> 7, d = i & 127;
        g_ex[(size_t)(m0 + r) * 256 + 128 + d] = __float2half(h0[(size_t)(m0 + r) * 128 + d]);
    }
}

// ============================================================
// 2) GEMM: gates[4096][512] = x @ W^T (single fp16, fp32 accum)
//    CTA 128x64, 256 thr, warp 32x32, BK=32, cp.async 3-stage,
//    ldmatrix + mma.sync.m16n8k16.f16. A gathered on-the-fly.
// ============================================================
#define LDP 40                          // padded leading dim (elements)
#define A_STAGE_B (TM * LDP * 2)        // 10240 bytes
#define B_STAGE_B (TN * LDP * 2)        // 5120 bytes
#define OFF_B     (A_STAGE_B)           // 10240
#define STAGE_B   (A_STAGE_B + B_STAGE_B)  // 15360
#define IDS_B     (128 * 60 * 2)        // 15360 (u16 id table)
#define SM_STG    IDS_B
#define GEMM_SMEM (IDS_B + NSTAGE * STAGE_B)   // 61440

__device__ __forceinline__ uint32_t smem_u32(const void* p) {
    uint32_t a;
    asm("{ .reg .u64 t; cvta.to.shared.u64 t, %1; cvt.u32.u64 %0, t; }" : "=r"(a) : "l"(p));
    return a;
}
__device__ __forceinline__ void cp16(uint32_t s, const void* g) {
    asm volatile("cp.async.cg.shared.global [%0], [%1], 16;" :: "r"(s), "l"(g));
}
#define LDSM4(r, addr) \
    asm volatile("ldmatrix.sync.aligned.m8n8.x4.shared.b16 {%0,%1,%2,%3}, [%4];" \
        : "=r"((r)[0]), "=r"((r)[1]), "=r"((r)[2]), "=r"((r)[3]) : "r"(addr))
#define MMAF16(c, a, b0, b1) \
    asm volatile("mma.sync.aligned.m16n8k16.row.col.f32.f16.f16.f32 " \
        "{%0,%1,%2,%3}, {%4,%5,%6,%7}, {%8,%9}, {%0,%1,%2,%3};" \
        : "+f"((c)[0]), "+f"((c)[1]), "+f"((c)[2]), "+f"((c)[3]) \
        : "r"((a)[0]), "r"((a)[1]), "r"((a)[2]), "r"((a)[3]), "r"(b0), "r"(b1))

__global__ __launch_bounds__(256, 2)
void gemm_kernel(const int* __restrict__ aid, const int* __restrict__ mid)
{
    extern __shared__ char smbase[];
    const uint32_t sb = smem_u32(smbase);
    const int tid = threadIdx.x;
    const int n0 = blockIdx.x * TN;
    const int m0 = blockIdx.y * TM;

    // ---- load id table: sid[r][0..11]=ability, sid[r][12..59]=move ----
    uint16_t* sid = (uint16_t*)smbase;
    {
        const int* asrc = aid + (size_t)m0 * 12;     // 1536 contiguous ints
        const int* msrc = mid + (size_t)m0 * 48;     // 6144 contiguous ints
        for (int i = tid; i < 1536; i += 256) {
            int r = i / 12, s = i % 12;
            sid[r * 60 + s] = (uint16_t)asrc[i];
        }
        for (int i = tid; i < 6144; i += 256) {
            int r = i / 48, s = i % 48;
            sid[r * 60 + 12 + s] = (uint16_t)msrc[i];
        }
    }
    __syncthreads();

    // ---- per-thread cp.async roles: A rows r0, r0+64, B row r0, chunk c ----
    const int r0 = tid >> 2;             // 0..63
    const int r1 = r0 + 64;
    const int c  = tid & 3;              // 16B chunk within 64B k-row
    const uint32_t soff_a0 = r0 * (LDP * 2) + c * 16;
    const uint32_t soff_a1 = r1 * (LDP * 2) + c * 16;
    const uint32_t soff_b  = OFF_B + r0 * (LDP * 2) + c * 16;
    const char* bsrc = (const char*)(g_w + (size_t)(n0 + r0) * K_EXT) + c * 16;

    auto prefetch = [&](int ss, int buf) {
        const uint32_t dst = sb + SM_STG + buf * STAGE_B;
        const int k = ss * BK + c * 8;
        const char *a0, *a1;
        if (k < 7680) {
            const int s = k >> 7, d = k & 127;
            const int id0 = sid[r0 * 60 + s];
            const int id1 = sid[r1 * 60 + s];
            if (s < 12) {
                a0 = (const char*)(g_ea + id0 * 128 + d);
                a1 = (const char*)(g_ea + id1 * 128 + d);
            } else {
                a0 = (const char*)(g_em + id0 * 128 + d);
                a1 = (const char*)(g_em + id1 * 128 + d);
            }
        } else {
            const int d = k - 7680;
            a0 = (const char*)(g_ex + (size_t)(m0 + r0) * 256 + d);
            a1 = (const char*)(g_ex + (size_t)(m0 + r1) * 256 + d);
        }
        cp16(dst + soff_a0, a0);
        cp16(dst + soff_a1, a1);
        cp16(dst + soff_b, bsrc + (size_t)ss * (BK * 2));
        asm volatile("cp.async.commit_group;" ::: "memory");
    };

    const int wid = tid >> 5;
    const int lane = tid & 31;
    const int wm = wid & 3;              // 4 warps along M (32 rows each)
    const int wn = wid >> 2;             // 2 warps along N (32 cols each)

    // ---- ldmatrix lane-address element offsets (within stage, in elements) ----
    const int arow = lane & 15;
    const int akh  = (lane >> 4) << 3;
    int aoff[2];
    #pragma unroll
    for (int i = 0; i < 2; i++)
        aoff[i] = (wm * 32 + i * 16 + arow) * LDP + akh;
    const int bn  = (lane & 7) + ((lane >> 4) << 3);
    const int bkh = ((lane >> 3) & 1) << 3;
    int boff[2];
    #pragma unroll
    for (int p = 0; p < 2; p++)
        boff[p] = (wn * 32 + p * 16 + bn) * LDP + bkh;

    float acc[2][4][4];   // [m-tile][n8-tile][frag]
    #pragma unroll
    for (int i = 0; i < 2; i++)
        #pragma unroll
        for (int j = 0; j < 4; j++)
            #pragma unroll
            for (int q = 0; q < 4; q++) acc[i][j][q] = 0.0f;

    // ---- prologue: stages 0,1 in flight ----
    prefetch(0, 0);
    prefetch(1, 1);

    #pragma unroll 1
    for (int t = 0; t < NT; ++t) {
        asm volatile("cp.async.wait_group 1;" ::: "memory");
        __syncthreads();   // stage t visible; all warps done with stage t-1

        if (t + 2 < NT) {
            prefetch(t + 2, (t + 2) % NSTAGE);
        } else {
            asm volatile("cp.async.commit_group;" ::: "memory");  // keep group count uniform
        }

        const uint32_t stg_u = sb + SM_STG + (t % NSTAGE) * STAGE_B;
        const uint32_t A_u = stg_u;
        const uint32_t B_u = stg_u + OFF_B;

        #pragma unroll
        for (int sub = 0; sub < 2; sub++) {
            const int k16 = sub * 16;
            uint32_t aa[2][4], bb[2][4];
            // 4 independent LDSM.x4 up front
            #pragma unroll
            for (int i = 0; i < 2; i++) LDSM4(aa[i], A_u + (uint32_t)(aoff[i] + k16) * 2);
            #pragma unroll
            for (int p = 0; p < 2; p++) LDSM4(bb[p], B_u + (uint32_t)(boff[p] + k16) * 2);
            // 8 MMAs across 8 independent accumulator tiles
            #pragma unroll
            for (int i = 0; i < 2; i++)
                #pragma unroll
                for (int j = 0; j < 4; j++) {
                    const int p = j >> 1, h = (j & 1) * 2;
                    MMAF16(acc[i][j], aa[i], bb[p][h], bb[p][h + 1]);
                }
        }
    }

    // ---- epilogue: direct coalesced STG from accumulators (tail adds biases) ----
    asm volatile("cp.async.wait_group 0;" ::: "memory");
    const int erow = lane >> 2;          // 0..7
    const int ecol = (lane & 3) * 2;     // 0,2,4,6
    #pragma unroll
    for (int i = 0; i < 2; i++) {
        #pragma unroll
        for (int j = 0; j < 4; j++) {
            const int gm = m0 + wm * 32 + i * 16 + erow;
            const int gn = n0 + wn * 32 + j * 8 + ecol;
            float2 v0{acc[i][j][0], acc[i][j][1]};
            float2 v1{acc[i][j][2], acc[i][j][3]};
            *(float2*)(g_gates + (size_t)gm * N_G + gn) = v0;
            *(float2*)(g_gates + (size_t)(gm + 8) * N_G + gn) = v1;
        }
    }
}

// ============================================================
// 3) tail: 16 rows per block, ALL rows processed in parallel per phase,
//    5 barriers total (R14 proven config).
// ============================================================
__device__ __forceinline__ float sigm(float x) { return 1.0f / (1.0f + expf(-x)); }

#define OFF_H1 (NB * 9)
#define OFF_C1 (NB * 9 + NB * 128)
#define TROWS  16

// dynamic smem float offsets
#define T_W1T   0                          // [128][65]
#define T_W2T   (T_W1T + 128 * 65)         // [64][129]
#define T_WAS   (T_W2T + 64 * 129)         // [9][129]
#define T_BSUM  (T_WAS + 9 * 129)          // [512]
#define T_B1    (T_BSUM + 512)             // [64]
#define T_B2    (T_B1 + 64)                // [128]
#define T_BA    (T_B2 + 128)               // [12]
#define T_H1S   (T_BA + 12)                // [16][132]
#define T_FE    (T_H1S + TROWS * 132)      // [16][68]
#define T_ES    (T_FE + TROWS * 68)        // [16][132]
#define T_LG    (T_ES + TROWS * 132)       // [16][12]
#define T_TOT   (T_LG + TROWS * 12)
#define TAIL_SMEM (T_TOT * 4)              // ~95.9 KB

__global__ __launch_bounds__(256)
void tail_kernel(const float* __restrict__ c0,
                 const float* __restrict__ bih, const float* __restrict__ bhh,
                 const float* __restrict__ W1, const float* __restrict__ b1,
                 const float* __restrict__ W2, const float* __restrict__ b2,
                 const float* __restrict__ Wa, const float* __restrict__ ba,
                 const float* __restrict__ mask, float* __restrict__ out)
{
    extern __shared__ float sm[];
    float* W1t  = sm + T_W1T;    // [d][j] stride 65
    float* W2t  = sm + T_W2T;    // [d][t] stride 129
    float* Was  = sm + T_WAS;    // [j][d] stride 129
    float* bsum = sm + T_BSUM;
    float* b1s  = sm + T_B1;
    float* b2s  = sm + T_B2;
    float* bas  = sm + T_BA;
    float* h1s  = sm + T_H1S;    // [r][t] stride 132
    float* fes  = sm + T_FE;     // [r][j] stride 68
    float* es   = sm + T_ES;     // [r][t] stride 132
    float* lgs  = sm + T_LG;     // [r][j] stride 12

    const int tid = threadIdx.x;
    const int b0 = blockIdx.x * TROWS;

    // ---- stage weights/biases (all coalesced reads) ----
    for (int i = tid; i < 64 * 128; i += 256) {   // W1 [64][128]
        int j = i >> 7, d = i & 127;
        W1t[d * 65 + j] = W1[i];
    }
    for (int i = tid; i < 128 * 64; i += 256) {   // W2 [128][64]
        int t = i >> 6, d = i & 63;
        W2t[d * 129 + t] = W2[i];
    }
    for (int i = tid; i < 9 * 128; i += 256) {    // Wa [9][128]
        int j = i >> 7, d = i & 127;
        Was[j * 129 + d] = Wa[i];
    }
    for (int i = tid; i < 512; i += 256) bsum[i] = bih[i] + bhh[i];
    if (tid < 64) b1s[tid] = b1[tid];
    if (tid < 128) b2s[tid] = b2[tid];
    if (tid < 9) bas[tid] = ba[tid];
    __syncthreads();

    // ---- phase 1: LSTM elementwise, 16 rows x 128 = 2048 items ----
    #pragma unroll
    for (int p = 0; p < 8; p++) {
        const int idx = p * 256 + tid;
        const int r = idx >> 7, t = idx & 127;
        const int b = b0 + r;
        const float* g = g_gates + (size_t)b * N_G;
        float ii = sigm(g[t] + bsum[t]);
        float ff = sigm(g[128 + t] + bsum[128 + t]);
        float gv = tanhf(g[256 + t] + bsum[256 + t]);
        float oo = sigm(g[384 + t] + bsum[384 + t]);
        float c1 = ff * c0[(size_t)b * 128 + t] + ii * gv;
        float h1 = oo * tanhf(c1);
        out[OFF_H1 + (size_t)b * 128 + t] = h1;
        out[OFF_C1 + (size_t)b * 128 + t] = c1;
        h1s[r * 132 + t] = h1;
    }
    __syncthreads();

    // ---- phase 2: feat = relu(h1 @ W1^T + b1), 16 x 64 = 1024 items ----
    #pragma unroll
    for (int p = 0; p < 4; p++) {
        const int idx = p * 256 + tid;
        const int r = idx >> 6, j = idx & 63;
        float a = b1s[j];
        const float* h = h1s + r * 132;
        #pragma unroll 8
        for (int d = 0; d < 128; d++) a += W1t[d * 65 + j] * h[d];
        fes[r * 68 + j] = fmaxf(a, 0.0f);
    }
    __syncthreads();

    // ---- phase 3: e = feat @ W2^T + b2, 16 x 128 = 2048 items ----
    #pragma unroll
    for (int p = 0; p < 8; p++) {
        const int idx = p * 256 + tid;
        const int r = idx >> 7, t = idx & 127;
        float a = b2s[t];
        const float* f = fes + r * 68;
        #pragma unroll 8
        for (int d = 0; d < 64; d++) a += W2t[d * 129 + t] * f[d];
        es[r * 132 + t] = a;
    }
    __syncthreads();

    // ---- phase 4: logits = e @ Wa^T + ba, 16 x 9 = 144 items ----
    if (tid < 144) {
        const int r = tid / 9, j = tid - r * 9;
        float a = bas[j];
        const float* w = Was + j * 129;
        const float* e = es + r * 132;
        #pragma unroll 8
        for (int d = 0; d < 128; d++) a += w[d] * e[d];
        lgs[r * 12 + j] = a;
    }
    __syncthreads();

    // ---- phase 5: softmax + masked renorm, one thread per row ----
    if (tid < TROWS) {
        const int r = tid, b = b0 + r;
        float lg[9];
        float mx = -1e30f;
        #pragma unroll
        for (int j = 0; j < 9; j++) { lg[j] = lgs[r * 12 + j]; mx = fmaxf(mx, lg[j]); }
        float se = 0.0f;
        #pragma unroll
        for (int j = 0; j < 9; j++) { lg[j] = expf(lg[j] - mx); se += lg[j]; }
        float inv = 1.0f / se;
        float p[9], mk[9], msum = 0.0f;
        #pragma unroll
        for (int j = 0; j < 9; j++) {
            p[j] = lg[j] * inv;
            mk[j] = p[j] * mask[(size_t)b * 9 + j];
            msum += mk[j];
        }
        if (msum > 0.0f) {
            float minv = 1.0f / msum;
            #pragma unroll
            for (int j = 0; j < 9; j++) out[(size_t)b * 9 + j] = mk[j] * minv;
        } else {
            #pragma unroll
            for (int j = 0; j < 9; j++) out[(size_t)b * 9 + j] = p[j];
        }
    }
}

// ============================================================
// launcher
// ============================================================
extern "C" void kernel_launch(void* const* d_in, const int* in_sizes, int n_in,
                              void* d_out, int out_size)
{
    const int*   ability_ids = (const int*)d_in[0];
    const int*   move_ids    = (const int*)d_in[1];
    const float* numerical   = (const float*)d_in[2];
    const float* mask        = (const float*)d_in[3];
    const float* h0          = (const float*)d_in[4];
    const float* c0          = (const float*)d_in[5];
    const float* ability_emb = (const float*)d_in[6];
    const float* move_emb    = (const float*)d_in[7];
    const float* num_W       = (const float*)d_in[8];
    const float* num_b       = (const float*)d_in[9];
    const float* Wih         = (const float*)d_in[10];
    const float* Whh         = (const float*)d_in[11];
    const float* bih         = (const float*)d_in[12];
    const float* bhh         = (const float*)d_in[13];
    const float* W1          = (const float*)d_in[14];
    const float* b1          = (const float*)d_in[15];
    const float* W2          = (const float*)d_in[16];
    const float* b2          = (const float*)d_in[17];
    const float* Wa          = (const float*)d_in[18];
    const float* ba          = (const float*)d_in[19];
    float* out = (float*)d_out;

    cudaFuncSetAttribute(gemm_kernel, cudaFuncAttributeMaxDynamicSharedMemorySize, GEMM_SMEM);
    cudaFuncSetAttribute(pack_extra_kernel, cudaFuncAttributeMaxDynamicSharedMemorySize, EX_SMEM);
    cudaFuncSetAttribute(tail_kernel, cudaFuncAttributeMaxDynamicSharedMemorySize, TAIL_SMEM);

    pack_stream_kernel<<<1112, 256>>>(ability_emb, move_emb, Wih, Whh);
    pack_extra_kernel<<<NB / 32, 256, EX_SMEM>>>(numerical, num_W, num_b, h0);
    gemm_kernel<<<dim3(N_G / TN, NB / TM), 256, GEMM_SMEM>>>(ability_ids, move_ids);
    tail_kernel<<<NB / TROWS, 256, TAIL_SMEM>>>(c0, bih, bhh, W1, b1, W2, b2, Wa, ba, mask, out);
}

// round 17
// speedup vs baseline: 4.1004x; 1.1971x over previous
#include <cuda_runtime.h>
#include <cuda_fp16.h>
#include <math.h>
#include <stdint.h>

#define NB     4096          // batch rows
#define K_EXT  7936          // 7808 + 128 (h0 folded in)
#define N_G    512           // 4*LSTM_HIDDEN
#define TM     128
#define TN     64
#define BK     64
#define NSTAGE 3
#define NT     (K_EXT/BK)    // 124

// ---- scratch (device globals: allocation-free rule) ----
__device__ __align__(16) __half g_ea[300 * 128];    // ability emb (fp16)
__device__ __align__(16) __half g_em[900 * 128];    // move emb
__device__ __align__(16) __half g_ex[(size_t)NB * 256];   // [num | h0]
__device__ __align__(16) __half g_w[(size_t)N_G * K_EXT]; // W fp16 [N][K]
__device__ __align__(16) float  g_gates[(size_t)NB * N_G];  // fp32 gates (no bias)

// ============================================================
// 1a) pack_stream: embpack + wpack, NO dynamic smem (occupancy uncapped)
// ============================================================
__global__ __launch_bounds__(256)
void pack_stream_kernel(const float* __restrict__ aemb, const float* __restrict__ memb,
                        const float* __restrict__ Wih, const float* __restrict__ Whh)
{
    const int bx = blockIdx.x;
    const int tid = threadIdx.x;

    if (bx < 600) {
        // ---- embpack: 2 rows of the emb tables per block (single fp16) ----
        const int r = bx * 2 + (tid >> 7), t = tid & 127;
        if (r < 300) {
            g_ea[r * 128 + t] = __float2half(aemb[r * 128 + t]);
        } else {
            int rr = r - 300;
            g_em[rr * 128 + t] = __float2half(memb[rr * 128 + t]);
        }
    } else {
        // ---- wpack: one [Wih|Whh] row -> single fp16 ----
        const int n = bx - 600;
        for (int i4 = tid; i4 < K_EXT / 4; i4 += 256) {
            int k = i4 * 4;
            float4 v = (k < 7808) ? *(const float4*)(Wih + (size_t)n * 7808 + k)
                                  : *(const float4*)(Whh + n * 128 + (k - 7808));
            __half2 p01{__float2half(v.x), __float2half(v.y)};
            __half2 p23{__float2half(v.z), __float2half(v.w)};
            uint2 u;
            u.x = *(uint32_t*)&p01; u.y = *(uint32_t*)&p23;
            *(uint2*)(g_w + (size_t)n * K_EXT + k) = u;
        }
    }
}

// ============================================================
// 1b) pack_extra: numproj + h0 -> [B][256] single fp16 (needs 54KB smem)
// ============================================================
#define EX_SMEM ((128 * 85 + 32 * 84) * 4)   // 54272 bytes

__global__ __launch_bounds__(256)
void pack_extra_kernel(const float* __restrict__ numerical, const float* __restrict__ num_W,
                       const float* __restrict__ num_b, const float* __restrict__ h0)
{
    extern __shared__ float exsm[];
    float* Ws  = exsm;               // [128][85]
    float* nrs = exsm + 128 * 85;    // [32][84]
    const int tid = threadIdx.x;
    const int m0 = blockIdx.x * 32;

    for (int i = tid; i < 128 * 84; i += 256) {
        int t = i / 84, d = i - t * 84;
        Ws[t * 85 + d] = num_W[i];
    }
    for (int i = tid; i < 32 * 84; i += 256)
        nrs[i] = numerical[(size_t)m0 * 84 + i];
    __syncthreads();

    const int t = tid & 127, rbase = tid >> 7;
    const float nb = num_b[t];
    const float* w = Ws + t * 85;
    for (int rr = rbase; rr < 32; rr += 2) {
        const float* nr = nrs + rr * 84;
        float acc = nb;
        #pragma unroll 4
        for (int d = 0; d < 84; d++) acc += w[d] * nr[d];
        g_ex[(size_t)(m0 + rr) * 256 + t] = __float2half(acc);
    }
    for (int i = tid; i < 32 * 128; i += 256) {
        int r = i >> 7, d = i & 127;
        g_ex[(size_t)(m0 + r) * 256 + 128 + d] = __float2half(h0[(size_t)(m0 + r) * 128 + d]);
    }
}

// ============================================================
// 2) GEMM: gates[4096][512] = x @ W^T (single fp16, fp32 accum)
//    CTA 128x64, 256 thr, warp 32x32, BK=64 (half the barriers of R16),
//    cp.async 3-stage, ldmatrix + mma.sync.m16n8k16.f16.
// ============================================================
#define LDP 72                          // padded leading dim (elements)
#define A_STAGE_B (TM * LDP * 2)        // 18432 bytes
#define B_STAGE_B (TN * LDP * 2)        // 9216 bytes
#define OFF_B     (A_STAGE_B)           // 18432
#define STAGE_B   (A_STAGE_B + B_STAGE_B)  // 27648
#define IDS_B     (128 * 60 * 2)        // 15360 (u16 id table)
#define SM_STG    IDS_B
#define GEMM_SMEM (IDS_B + NSTAGE * STAGE_B)   // 98304

__device__ __forceinline__ uint32_t smem_u32(const void* p) {
    uint32_t a;
    asm("{ .reg .u64 t; cvta.to.shared.u64 t, %1; cvt.u32.u64 %0, t; }" : "=r"(a) : "l"(p));
    return a;
}
__device__ __forceinline__ void cp16(uint32_t s, const void* g) {
    asm volatile("cp.async.cg.shared.global [%0], [%1], 16;" :: "r"(s), "l"(g));
}
#define LDSM4(r, addr) \
    asm volatile("ldmatrix.sync.aligned.m8n8.x4.shared.b16 {%0,%1,%2,%3}, [%4];" \
        : "=r"((r)[0]), "=r"((r)[1]), "=r"((r)[2]), "=r"((r)[3]) : "r"(addr))
#define MMAF16(c, a, b0, b1) \
    asm volatile("mma.sync.aligned.m16n8k16.row.col.f32.f16.f16.f32 " \
        "{%0,%1,%2,%3}, {%4,%5,%6,%7}, {%8,%9}, {%0,%1,%2,%3};" \
        : "+f"((c)[0]), "+f"((c)[1]), "+f"((c)[2]), "+f"((c)[3]) \
        : "r"((a)[0]), "r"((a)[1]), "r"((a)[2]), "r"((a)[3]), "r"(b0), "r"(b1))

__global__ __launch_bounds__(256, 2)
void gemm_kernel(const int* __restrict__ aid, const int* __restrict__ mid)
{
    extern __shared__ char smbase[];
    const uint32_t sb = smem_u32(smbase);
    const int tid = threadIdx.x;
    const int n0 = blockIdx.x * TN;
    const int m0 = blockIdx.y * TM;

    // ---- load id table: sid[r][0..11]=ability, sid[r][12..59]=move ----
    uint16_t* sid = (uint16_t*)smbase;
    {
        const int* asrc = aid + (size_t)m0 * 12;     // 1536 contiguous ints
        const int* msrc = mid + (size_t)m0 * 48;     // 6144 contiguous ints
        for (int i = tid; i < 1536; i += 256) {
            int r = i / 12, s = i % 12;
            sid[r * 60 + s] = (uint16_t)asrc[i];
        }
        for (int i = tid; i < 6144; i += 256) {
            int r = i / 48, s = i % 48;
            sid[r * 60 + 12 + s] = (uint16_t)msrc[i];
        }
    }
    __syncthreads();

    // ---- per-thread cp.async roles: A rows r0+{0,32,64,96}, B rows r0+{0,32}, chunk c ----
    const int r0 = tid >> 3;             // 0..31
    const int c  = tid & 7;              // 16B chunk within 128B k-row
    uint32_t soff_a[4], soff_b[2];
    #pragma unroll
    for (int q = 0; q < 4; q++) soff_a[q] = (r0 + 32 * q) * (LDP * 2) + c * 16;
    #pragma unroll
    for (int q = 0; q < 2; q++) soff_b[q] = OFF_B + (r0 + 32 * q) * (LDP * 2) + c * 16;
    const char* bsrc[2] = {
        (const char*)(g_w + (size_t)(n0 + r0) * K_EXT) + c * 16,
        (const char*)(g_w + (size_t)(n0 + r0 + 32) * K_EXT) + c * 16 };

    auto prefetch = [&](int ss, int buf) {
        const uint32_t dst = sb + SM_STG + buf * STAGE_B;
        const int k = ss * BK + c * 8;
        #pragma unroll
        for (int q = 0; q < 4; q++) {
            const int rr = r0 + 32 * q;
            const char* a;
            if (ss < 120) {
                const int s = k >> 7, d = k & 127;
                const int id = sid[rr * 60 + s];
                a = (const char*)((s < 12 ? g_ea : g_em) + id * 128 + d);
            } else {
                a = (const char*)(g_ex + (size_t)(m0 + rr) * 256 + (k - 7680));
            }
            cp16(dst + soff_a[q], a);
        }
        const size_t bk = (size_t)ss * (BK * 2);
        #pragma unroll
        for (int q = 0; q < 2; q++)
            cp16(dst + soff_b[q], bsrc[q] + bk);
        asm volatile("cp.async.commit_group;" ::: "memory");
    };

    const int wid = tid >> 5;
    const int lane = tid & 31;
    const int wm = wid & 3;              // 4 warps along M (32 rows each)
    const int wn = wid >> 2;             // 2 warps along N (32 cols each)

    // ---- ldmatrix lane-address element offsets (within stage, in elements) ----
    const int arow = lane & 15;
    const int akh  = (lane >> 4) << 3;
    int aoff[2];
    #pragma unroll
    for (int i = 0; i < 2; i++)
        aoff[i] = (wm * 32 + i * 16 + arow) * LDP + akh;
    const int bn  = (lane & 7) + ((lane >> 4) << 3);
    const int bkh = ((lane >> 3) & 1) << 3;
    int boff[2];
    #pragma unroll
    for (int p = 0; p < 2; p++)
        boff[p] = (wn * 32 + p * 16 + bn) * LDP + bkh;

    float acc[2][4][4];   // [m-tile][n8-tile][frag]
    #pragma unroll
    for (int i = 0; i < 2; i++)
        #pragma unroll
        for (int j = 0; j < 4; j++)
            #pragma unroll
            for (int q = 0; q < 4; q++) acc[i][j][q] = 0.0f;

    // ---- prologue: stages 0,1 in flight ----
    prefetch(0, 0);
    prefetch(1, 1);

    #pragma unroll 1
    for (int t = 0; t < NT; ++t) {
        asm volatile("cp.async.wait_group 1;" ::: "memory");
        __syncthreads();   // stage t visible; all warps done with stage t-1

        if (t + 2 < NT) {
            prefetch(t + 2, (t + 2) % NSTAGE);
        } else {
            asm volatile("cp.async.commit_group;" ::: "memory");  // keep group count uniform
        }

        const uint32_t stg_u = sb + SM_STG + (t % NSTAGE) * STAGE_B;
        const uint32_t A_u = stg_u;
        const uint32_t B_u = stg_u + OFF_B;

        #pragma unroll
        for (int sub = 0; sub < 4; sub++) {
            const int k16 = sub * 16;
            uint32_t aa[2][4], bb[2][4];
            // 4 independent LDSM.x4 up front
            #pragma unroll
            for (int i = 0; i < 2; i++) LDSM4(aa[i], A_u + (uint32_t)(aoff[i] + k16) * 2);
            #pragma unroll
            for (int p = 0; p < 2; p++) LDSM4(bb[p], B_u + (uint32_t)(boff[p] + k16) * 2);
            // 8 MMAs across 8 independent accumulator tiles
            #pragma unroll
            for (int i = 0; i < 2; i++)
                #pragma unroll
                for (int j = 0; j < 4; j++) {
                    const int p = j >> 1, h = (j & 1) * 2;
                    MMAF16(acc[i][j], aa[i], bb[p][h], bb[p][h + 1]);
                }
        }
    }

    // ---- epilogue: direct coalesced STG from accumulators (tail adds biases) ----
    asm volatile("cp.async.wait_group 0;" ::: "memory");
    const int erow = lane >> 2;          // 0..7
    const int ecol = (lane & 3) * 2;     // 0,2,4,6
    #pragma unroll
    for (int i = 0; i < 2; i++) {
        #pragma unroll
        for (int j = 0; j < 4; j++) {
            const int gm = m0 + wm * 32 + i * 16 + erow;
            const int gn = n0 + wn * 32 + j * 8 + ecol;
            float2 v0{acc[i][j][0], acc[i][j][1]};
            float2 v1{acc[i][j][2], acc[i][j][3]};
            *(float2*)(g_gates + (size_t)gm * N_G + gn) = v0;
            *(float2*)(g_gates + (size_t)(gm + 8) * N_G + gn) = v1;
        }
    }
}

// ============================================================
// 3) tail: 16 rows per block, phase-parallel, 5 barriers.
//    R17: float4-vectorized matvec phases (weights row-major in smem,
//    strides ≡ 4 mod 32 -> conflict-free float4 lane access).
// ============================================================
__device__ __forceinline__ float sigm(float x) { return 1.0f / (1.0f + expf(-x)); }

#define OFF_H1 (NB * 9)
#define OFF_C1 (NB * 9 + NB * 128)
#define TROWS  16

// dynamic smem float offsets (all multiples of 4 -> 16B aligned)
#define T_W1V   0                          // [64][132]
#define T_W2V   (T_W1V + 64 * 132)         // [128][68]
#define T_WAS   (T_W2V + 128 * 68)         // [9][132]
#define T_BSUM  (T_WAS + 9 * 132)          // [512]
#define T_B1    (T_BSUM + 512)             // [64]
#define T_B2    (T_B1 + 64)                // [128]
#define T_BA    (T_B2 + 128)               // [12]
#define T_H1S   (T_BA + 12)                // [16][132]
#define T_FE    (T_H1S + TROWS * 132)      // [16][68]
#define T_ES    (T_FE + TROWS * 68)        // [16][132]
#define T_LG    (T_ES + TROWS * 132)       // [16][12]
#define T_TOT   (T_LG + TROWS * 12)
#define TAIL_SMEM (T_TOT * 4)              // ~96 KB

__global__ __launch_bounds__(256)
void tail_kernel(const float* __restrict__ c0,
                 const float* __restrict__ bih, const float* __restrict__ bhh,
                 const float* __restrict__ W1, const float* __restrict__ b1,
                 const float* __restrict__ W2, const float* __restrict__ b2,
                 const float* __restrict__ Wa, const float* __restrict__ ba,
                 const float* __restrict__ mask, float* __restrict__ out)
{
    extern __shared__ float sm[];
    float* W1v  = sm + T_W1V;    // [j][d] stride 132
    float* W2v  = sm + T_W2V;    // [t][d] stride 68
    float* Was  = sm + T_WAS;    // [j][d] stride 132
    float* bsum = sm + T_BSUM;
    float* b1s  = sm + T_B1;
    float* b2s  = sm + T_B2;
    float* bas  = sm + T_BA;
    float* h1s  = sm + T_H1S;    // [r][t] stride 132
    float* fes  = sm + T_FE;     // [r][j] stride 68
    float* es   = sm + T_ES;     // [r][t] stride 132
    float* lgs  = sm + T_LG;     // [r][j] stride 12

    const int tid = threadIdx.x;
    const int b0 = blockIdx.x * TROWS;

    // ---- stage weights/biases (all coalesced reads) ----
    for (int i = tid; i < 64 * 128; i += 256) {   // W1 [64][128]
        int j = i >> 7, d = i & 127;
        W1v[j * 132 + d] = W1[i];
    }
    for (int i = tid; i < 128 * 64; i += 256) {   // W2 [128][64]
        int t = i >> 6, d = i & 63;
        W2v[t * 68 + d] = W2[i];
    }
    for (int i = tid; i < 9 * 128; i += 256) {    // Wa [9][128]
        int j = i >> 7, d = i & 127;
        Was[j * 132 + d] = Wa[i];
    }
    for (int i = tid; i < 512; i += 256) bsum[i] = bih[i] + bhh[i];
    if (tid < 64) b1s[tid] = b1[tid];
    if (tid < 128) b2s[tid] = b2[tid];
    if (tid < 9) bas[tid] = ba[tid];
    __syncthreads();

    // ---- phase 1: LSTM elementwise, 16 rows x 128 = 2048 items ----
    #pragma unroll
    for (int p = 0; p < 8; p++) {
        const int idx = p * 256 + tid;
        const int r = idx >> 7, t = idx & 127;
        const int b = b0 + r;
        const float* g = g_gates + (size_t)b * N_G;
        float ii = sigm(g[t] + bsum[t]);
        float ff = sigm(g[128 + t] + bsum[128 + t]);
        float gv = tanhf(g[256 + t] + bsum[256 + t]);
        float oo = sigm(g[384 + t] + bsum[384 + t]);
        float c1 = ff * c0[(size_t)b * 128 + t] + ii * gv;
        float h1 = oo * tanhf(c1);
        out[OFF_H1 + (size_t)b * 128 + t] = h1;
        out[OFF_C1 + (size_t)b * 128 + t] = c1;
        h1s[r * 132 + t] = h1;
    }
    __syncthreads();

    // ---- phase 2: feat = relu(h1 @ W1^T + b1), float4, 16 x 64 items ----
    #pragma unroll
    for (int p = 0; p < 4; p++) {
        const int idx = p * 256 + tid;
        const int r = idx >> 6, j = idx & 63;
        float a = b1s[j];
        const float4* wv = (const float4*)(W1v + j * 132);
        const float4* hv = (const float4*)(h1s + r * 132);
        #pragma unroll 8
        for (int d4 = 0; d4 < 32; d4++) {
            float4 w = wv[d4], h = hv[d4];
            a += w.x * h.x + w.y * h.y + w.z * h.z + w.w * h.w;
        }
        fes[r * 68 + j] = fmaxf(a, 0.0f);
    }
    __syncthreads();

    // ---- phase 3: e = feat @ W2^T + b2, float4, 16 x 128 items ----
    #pragma unroll
    for (int p = 0; p < 8; p++) {
        const int idx = p * 256 + tid;
        const int r = idx >> 7, t = idx & 127;
        float a = b2s[t];
        const float4* wv = (const float4*)(W2v + t * 68);
        const float4* fv = (const float4*)(fes + r * 68);
        #pragma unroll 8
        for (int d4 = 0; d4 < 16; d4++) {
            float4 w = wv[d4], f = fv[d4];
            a += w.x * f.x + w.y * f.y + w.z * f.z + w.w * f.w;
        }
        es[r * 132 + t] = a;
    }
    __syncthreads();

    // ---- phase 4: logits = e @ Wa^T + ba, float4, 16 x 9 = 144 items ----
    if (tid < 144) {
        const int r = tid / 9, j = tid - r * 9;
        float a = bas[j];
        const float4* wv = (const float4*)(Was + j * 132);
        const float4* ev = (const float4*)(es + r * 132);
        #pragma unroll 8
        for (int d4 = 0; d4 < 32; d4++) {
            float4 w = wv[d4], e = ev[d4];
            a += w.x * e.x + w.y * e.y + w.z * e.z + w.w * e.w;
        }
        lgs[r * 12 + j] = a;
    }
    __syncthreads();

    // ---- phase 5: softmax + masked renorm, one thread per row ----
    if (tid < TROWS) {
        const int r = tid, b = b0 + r;
        float lg[9];
        float mx = -1e30f;
        #pragma unroll
        for (int j = 0; j < 9; j++) { lg[j] = lgs[r * 12 + j]; mx = fmaxf(mx, lg[j]); }
        float se = 0.0f;
        #pragma unroll
        for (int j = 0; j < 9; j++) { lg[j] = expf(lg[j] - mx); se += lg[j]; }
        float inv = 1.0f / se;
        float p[9], mk[9], msum = 0.0f;
        #pragma unroll
        for (int j = 0; j < 9; j++) {
            p[j] = lg[j] * inv;
            mk[j] = p[j] * mask[(size_t)b * 9 + j];
            msum += mk[j];
        }
        if (msum > 0.0f) {
            float minv = 1.0f / msum;
            #pragma unroll
            for (int j = 0; j < 9; j++) out[(size_t)b * 9 + j] = mk[j] * minv;
        } else {
            #pragma unroll
            for (int j = 0; j < 9; j++) out[(size_t)b * 9 + j] = p[j];
        }
    }
}

// ============================================================
// launcher
// ============================================================
extern "C" void kernel_launch(void* const* d_in, const int* in_sizes, int n_in,
                              void* d_out, int out_size)
{
    const int*   ability_ids = (const int*)d_in[0];
    const int*   move_ids    = (const int*)d_in[1];
    const float* numerical   = (const float*)d_in[2];
    const float* mask        = (const float*)d_in[3];
    const float* h0          = (const float*)d_in[4];
    const float* c0          = (const float*)d_in[5];
    const float* ability_emb = (const float*)d_in[6];
    const float* move_emb    = (const float*)d_in[7];
    const float* num_W       = (const float*)d_in[8];
    const float* num_b       = (const float*)d_in[9];
    const float* Wih         = (const float*)d_in[10];
    const float* Whh         = (const float*)d_in[11];
    const float* bih         = (const float*)d_in[12];
    const float* bhh         = (const float*)d_in[13];
    const float* W1          = (const float*)d_in[14];
    const float* b1          = (const float*)d_in[15];
    const float* W2          = (const float*)d_in[16];
    const float* b2          = (const float*)d_in[17];
    const float* Wa          = (const float*)d_in[18];
    const float* ba          = (const float*)d_in[19];
    float* out = (float*)d_out;

    cudaFuncSetAttribute(gemm_kernel, cudaFuncAttributeMaxDynamicSharedMemorySize, GEMM_SMEM);
    cudaFuncSetAttribute(pack_extra_kernel, cudaFuncAttributeMaxDynamicSharedMemorySize, EX_SMEM);
    cudaFuncSetAttribute(tail_kernel, cudaFuncAttributeMaxDynamicSharedMemorySize, TAIL_SMEM);

    pack_stream_kernel<<<1112, 256>>>(ability_emb, move_emb, Wih, Whh);
    pack_extra_kernel<<<NB / 32, 256, EX_SMEM>>>(numerical, num_W, num_b, h0);
    gemm_kernel<<<dim3(N_G / TN, NB / TM), 256, GEMM_SMEM>>>(ability_ids, move_ids);
    tail_kernel<<<NB / TROWS, 256, TAIL_SMEM>>>(c0, bih, bhh, W1, b1, W2, b2, Wa, ba, mask, out);
}